// round 4
// baseline (speedup 1.0000x reference)
#include <cuda_runtime.h>
#include <cstdint>

#define DEVI __device__ __forceinline__

// ---- problem constants ----
#define NB 4
#define NL 2048
#define ND 512
#define NH 8
#define HD 64
#define NBH (NB*NH)

// ---- scratch (static device globals: the sanctioned scratch mechanism) ----
static __device__ float g_q[(size_t)NB * NH * NL * HD];
static __device__ float g_k[(size_t)NB * NH * NL * HD];
static __device__ float g_v[(size_t)NB * NH * NL * HD];
static __device__ float g_ctx[(size_t)NB * NL * ND];
static __device__ float g_final[(size_t)NB * NL * ND];
static __device__ float g_attn[(size_t)NB * NH * NL * NL];   // fallback if attn not in d_out

// ---- small PTX helpers ----
DEVI uint32_t f2tf(float f) {
    uint32_t u;
    asm volatile("cvt.rna.tf32.f32 %0, %1;" : "=r"(u) : "f"(f));
    return u;
}

DEVI void mma_tf32(float c[4], const uint32_t a[4], const uint32_t b[2]) {
    asm volatile(
        "mma.sync.aligned.m16n8k8.row.col.f32.tf32.tf32.f32 "
        "{%0,%1,%2,%3},{%4,%5,%6,%7},{%8,%9},{%0,%1,%2,%3};"
        : "+f"(c[0]), "+f"(c[1]), "+f"(c[2]), "+f"(c[3])
        : "r"(a[0]), "r"(a[1]), "r"(a[2]), "r"(a[3]), "r"(b[0]), "r"(b[1]));
}

DEVI void cpa16(float* s, const float* g) {
    uint32_t sa = (uint32_t)__cvta_generic_to_shared(s);
    asm volatile("cp.async.cg.shared.global [%0], [%1], 16;" :: "r"(sa), "l"(g));
}
DEVI void cp_commit() { asm volatile("cp.async.commit_group;"); }
template <int N> DEVI void cp_wait() { asm volatile("cp.async.wait_group %0;" :: "n"(N)); }

// ============================================================================
// TN GEMM: out[m,n] = sum_k A[m,k] * W[n,k] + bias[n]
//   M = NB*NL = 8192, N = 512, K = 512.
//   PERM=1: write out as [B, H, L, 64] head-split layout (QKV projections).
//   PERM=0: write out as [M, 512] row-major (output projection / context).
// BM=128, BN=128, BK=32, 256 threads (8 warps, warp tile 32x64), TF32 mma.
// smem layout: As/Bs [2][128][36] (pad 4 -> stride%32==4, conflict-free frags)
// ============================================================================
template <int PERM>
__global__ __launch_bounds__(256, 1) void gemm_tn(
    const float* __restrict__ A, const float* __restrict__ W,
    const float* __restrict__ bias, float* __restrict__ out)
{
    extern __shared__ float sm[];
    float* As = sm;                  // [2][128][36]
    float* Bs = sm + 2 * 128 * 36;   // [2][128][36]
    const int tid  = threadIdx.x;
    const int lane = tid & 31, wid = tid >> 5;
    const int wm = wid & 3, wn = wid >> 2;
    const int m0 = blockIdx.x * 128, n0 = blockIdx.y * 128;

    float acc[2][8][4];
#pragma unroll
    for (int i = 0; i < 2; i++)
#pragma unroll
        for (int j = 0; j < 8; j++)
#pragma unroll
            for (int e = 0; e < 4; e++) acc[i][j][e] = 0.f;

    const int lr = tid >> 3, lc = (tid & 7) * 4;

    auto load_tile = [&](int buf, int kt) {
        const float* ag = A + (size_t)m0 * 512 + kt * 32;
        const float* bg = W + (size_t)n0 * 512 + kt * 32;
#pragma unroll
        for (int i = 0; i < 4; i++) {
            int r = lr + 32 * i;
            cpa16(&As[buf * 4608 + r * 36 + lc], ag + (size_t)r * 512 + lc);
            cpa16(&Bs[buf * 4608 + r * 36 + lc], bg + (size_t)r * 512 + lc);
        }
        cp_commit();
    };

    load_tile(0, 0);
    for (int kt = 0; kt < 16; kt++) {
        if (kt < 15) { load_tile((kt + 1) & 1, kt + 1); cp_wait<1>(); }
        else         { cp_wait<0>(); }
        __syncthreads();
        const float* as = &As[(kt & 1) * 4608];
        const float* bs = &Bs[(kt & 1) * 4608];
#pragma unroll
        for (int kk = 0; kk < 4; kk++) {
            int k0 = kk * 8 + (lane & 3);
            uint32_t af[2][4], bf[8][2];
#pragma unroll
            for (int i = 0; i < 2; i++) {
                int m = wm * 32 + i * 16 + (lane >> 2);
                af[i][0] = f2tf(as[m * 36 + k0]);
                af[i][1] = f2tf(as[(m + 8) * 36 + k0]);
                af[i][2] = f2tf(as[m * 36 + k0 + 4]);
                af[i][3] = f2tf(as[(m + 8) * 36 + k0 + 4]);
            }
#pragma unroll
            for (int j = 0; j < 8; j++) {
                int n = wn * 64 + j * 8 + (lane >> 2);
                bf[j][0] = f2tf(bs[n * 36 + k0]);
                bf[j][1] = f2tf(bs[n * 36 + k0 + 4]);
            }
#pragma unroll
            for (int i = 0; i < 2; i++)
#pragma unroll
                for (int j = 0; j < 8; j++) mma_tf32(acc[i][j], af[i], bf[j]);
        }
        __syncthreads();
    }

#pragma unroll
    for (int i = 0; i < 2; i++)
#pragma unroll
        for (int j = 0; j < 8; j++)
#pragma unroll
            for (int e = 0; e < 4; e++) {
                int row = m0 + wm * 32 + i * 16 + (lane >> 2) + ((e >> 1) * 8);
                int col = n0 + wn * 64 + j * 8 + ((lane & 3) * 2) + (e & 1);
                float v = acc[i][j][e] + __ldg(&bias[col]);
                if (PERM) {
                    int bb = row >> 11, l = row & (NL - 1);
                    out[(((size_t)(bb * NH + (col >> 6))) * NL + l) * HD + (col & 63)] = v;
                } else {
                    out[(size_t)row * ND + col] = v;
                }
            }
}

// ============================================================================
// Scores + softmax: per CTA 16 q rows x full L keys kept in smem.
//   S = Q K^T (TF32 mma), then s = S*0.125 - 1e30*mask, row softmax, attn write.
// grid = (L/16, B*H), 256 threads.
// smem: Ssm [16][2052] + Ks [2][128][68] + Qs [16][68]  = 205,312 B
// ============================================================================
__global__ __launch_bounds__(256, 1) void scores_softmax(
    const float* __restrict__ Q, const float* __restrict__ K,
    const int* __restrict__ mask, float* __restrict__ attn)
{
    extern __shared__ float sm[];
    float* Ssm = sm;                   // [16][2052]
    float* Ks  = sm + 16 * 2052;       // [2][128][68]
    float* Qs  = Ks + 2 * 128 * 68;    // [16][68]
    const int tid = threadIdx.x, lane = tid & 31, wid = tid >> 5;
    const int bh = blockIdx.y, q0 = blockIdx.x * 16;

    const float* Qg = Q + ((size_t)bh * NL + q0) * HD;
    const float* Kg = K + (size_t)bh * NL * HD;

    {   // Q tile: 16 x 64, one float4 per thread (goes into cp.async group 0)
        int r = tid >> 4, c = (tid & 15) * 4;
        cpa16(&Qs[r * 68 + c], Qg + r * HD + c);
    }
    auto loadK = [&](int buf, int kt) {
#pragma unroll
        for (int i = 0; i < 8; i++) {
            int r = (tid >> 4) + 16 * i, c = (tid & 15) * 4;
            cpa16(&Ks[buf * 8704 + r * 68 + c], Kg + (size_t)(kt * 128 + r) * HD + c);
        }
        cp_commit();
    };
    loadK(0, 0);

    for (int kt = 0; kt < 16; kt++) {
        if (kt < 15) { loadK((kt + 1) & 1, kt + 1); cp_wait<1>(); }
        else         { cp_wait<0>(); }
        __syncthreads();
        const float* ks = &Ks[(kt & 1) * 8704];
        const int tw = wid * 16;            // 16 tokens per warp
        float acc[2][4] = {};
#pragma unroll
        for (int kk = 0; kk < 8; kk++) {
            int k0 = kk * 8 + (lane & 3);
            uint32_t af[4], bf[2][2];
            int r = lane >> 2;
            af[0] = f2tf(Qs[r * 68 + k0]);
            af[1] = f2tf(Qs[(r + 8) * 68 + k0]);
            af[2] = f2tf(Qs[r * 68 + k0 + 4]);
            af[3] = f2tf(Qs[(r + 8) * 68 + k0 + 4]);
#pragma unroll
            for (int j = 0; j < 2; j++) {
                int n = tw + j * 8 + (lane >> 2);
                bf[j][0] = f2tf(ks[n * 68 + k0]);
                bf[j][1] = f2tf(ks[n * 68 + k0 + 4]);
            }
            mma_tf32(acc[0], af, bf[0]);
            mma_tf32(acc[1], af, bf[1]);
        }
#pragma unroll
        for (int j = 0; j < 2; j++)
#pragma unroll
            for (int e = 0; e < 4; e++) {
                int r   = (lane >> 2) + ((e >> 1) * 8);
                int col = kt * 128 + tw + j * 8 + (lane & 3) * 2 + (e & 1);
                Ssm[r * 2052 + col] = acc[j][e];
            }
        __syncthreads();
    }

    // masked softmax, one warp handles 2 rows
    const int b = bh >> 3;
#pragma unroll
    for (int rr = 0; rr < 2; rr++) {
        int r = wid * 2 + rr;
        float* srow = &Ssm[r * 2052];
        const int* mrow = mask + ((size_t)b * NL + q0 + r) * NL;
        float mx = -3.4e38f;
        for (int i = lane; i < NL; i += 32) {
            float s = fmaf((float)mrow[i], -1e30f, srow[i] * 0.125f);
            srow[i] = s;
            mx = fmaxf(mx, s);
        }
#pragma unroll
        for (int o = 16; o > 0; o >>= 1) mx = fmaxf(mx, __shfl_xor_sync(0xffffffffu, mx, o));
        float l = 0.f;
        for (int i = lane; i < NL; i += 32) {
            float p = __expf(srow[i] - mx);
            srow[i] = p;
            l += p;
        }
#pragma unroll
        for (int o = 16; o > 0; o >>= 1) l += __shfl_xor_sync(0xffffffffu, l, o);
        float inv = 1.f / l;
        float* arow = attn + ((size_t)bh * NL + q0 + r) * NL;
        for (int i = lane; i < NL; i += 32) arow[i] = srow[i] * inv;
    }
}

// ============================================================================
// P·V: per (b,h), ctx[b,l,h*64+d] = sum_t attn[bh,l,t] * V[bh,t,d]
//   M=2048, N=64, K=2048. BM=128, BN=64, BK=32, 256 threads (warp tile 32x32).
// smem: As [2][128][36] + Vs [2][32][68] = 54,272 B
// ============================================================================
__global__ __launch_bounds__(256, 1) void pv_gemm(
    const float* __restrict__ attn, const float* __restrict__ V,
    float* __restrict__ ctx)
{
    extern __shared__ float sm[];
    float* As = sm;                  // [2][128][36]
    float* Vs = sm + 2 * 128 * 36;   // [2][32][68]
    const int tid = threadIdx.x, lane = tid & 31, wid = tid >> 5;
    const int wm = wid & 3, wn = wid >> 2;
    const int bh = blockIdx.y, m0 = blockIdx.x * 128;
    const int b = bh >> 3, h = bh & 7;
    const float* Ag = attn + (size_t)bh * NL * NL;
    const float* Vg = V + (size_t)bh * NL * HD;

    float acc[2][4][4];
#pragma unroll
    for (int i = 0; i < 2; i++)
#pragma unroll
        for (int j = 0; j < 4; j++)
#pragma unroll
            for (int e = 0; e < 4; e++) acc[i][j][e] = 0.f;

    auto load_tile = [&](int buf, int kt) {
#pragma unroll
        for (int i = 0; i < 4; i++) {
            int r = (tid >> 3) + 32 * i, c = (tid & 7) * 4;
            cpa16(&As[buf * 4608 + r * 36 + c], Ag + (size_t)(m0 + r) * NL + kt * 32 + c);
        }
#pragma unroll
        for (int i = 0; i < 2; i++) {
            int r = (tid >> 4) + 16 * i, c = (tid & 15) * 4;
            cpa16(&Vs[buf * 2176 + r * 68 + c], Vg + (size_t)(kt * 32 + r) * HD + c);
        }
        cp_commit();
    };

    load_tile(0, 0);
    for (int kt = 0; kt < 64; kt++) {
        if (kt < 63) { load_tile((kt + 1) & 1, kt + 1); cp_wait<1>(); }
        else         { cp_wait<0>(); }
        __syncthreads();
        const float* as = &As[(kt & 1) * 4608];
        const float* vs = &Vs[(kt & 1) * 2176];
#pragma unroll
        for (int kk = 0; kk < 4; kk++) {
            int k0 = kk * 8 + (lane & 3);
            uint32_t af[2][4], bf[4][2];
#pragma unroll
            for (int i = 0; i < 2; i++) {
                int m = wm * 32 + i * 16 + (lane >> 2);
                af[i][0] = f2tf(as[m * 36 + k0]);
                af[i][1] = f2tf(as[(m + 8) * 36 + k0]);
                af[i][2] = f2tf(as[m * 36 + k0 + 4]);
                af[i][3] = f2tf(as[(m + 8) * 36 + k0 + 4]);
            }
#pragma unroll
            for (int j = 0; j < 4; j++) {
                int n = wn * 32 + j * 8 + (lane >> 2);
                bf[j][0] = f2tf(vs[k0 * 68 + n]);
                bf[j][1] = f2tf(vs[(k0 + 4) * 68 + n]);
            }
#pragma unroll
            for (int i = 0; i < 2; i++)
#pragma unroll
                for (int j = 0; j < 4; j++) mma_tf32(acc[i][j], af[i], bf[j]);
        }
        __syncthreads();
    }

#pragma unroll
    for (int i = 0; i < 2; i++)
#pragma unroll
        for (int j = 0; j < 4; j++)
#pragma unroll
            for (int e = 0; e < 4; e++) {
                int l = m0 + wm * 32 + i * 16 + (lane >> 2) + ((e >> 1) * 8);
                int d = wn * 32 + j * 8 + (lane & 3) * 2 + (e & 1);
                ctx[((size_t)b * NL + l) * ND + h * HD + d] = acc[i][j][e];
            }
}

// ============================================================================
// launch
// ============================================================================
extern "C" void kernel_launch(void* const* d_in, const int* in_sizes, int n_in,
                              void* d_out, int out_size) {
    (void)in_sizes; (void)n_in;
    const float* x_q = (const float*)d_in[0];
    const float* x_k = (const float*)d_in[1];
    const float* x_v = (const float*)d_in[2];
    const int*   msk = (const int*)d_in[3];
    const float* Wq  = (const float*)d_in[4];
    const float* bq  = (const float*)d_in[5];
    const float* Wk  = (const float*)d_in[6];
    const float* bk  = (const float*)d_in[7];
    const float* Wv  = (const float*)d_in[8];
    const float* bv  = (const float*)d_in[9];
    const float* Wo  = (const float*)d_in[10];
    const float* bo  = (const float*)d_in[11];

    const long long FINAL_N = (long long)NB * NL * ND;              //   4,194,304
    const long long ATTN_N  = (long long)NB * NH * NL * NL;         // 134,217,728

    float* outp = (float*)d_out;
    float* finalp;
    float* attnp;
    if ((long long)out_size >= FINAL_N + ATTN_N) { finalp = outp; attnp = outp + FINAL_N; }
    else if ((long long)out_size == ATTN_N)      { attnp = outp;  finalp = g_final; }
    else                                         { finalp = outp; attnp = g_attn; }

    const int SM_GEMM   = 2 * (2 * 128 * 36) * 4;                   // 73,728 B
    const int SM_SCORES = (16 * 2052 + 2 * 128 * 68 + 16 * 68) * 4; // 205,312 B
    const int SM_PV     = (2 * 128 * 36 + 2 * 32 * 68) * 4;         // 54,272 B

    cudaFuncSetAttribute(gemm_tn<1>, cudaFuncAttributeMaxDynamicSharedMemorySize, SM_GEMM);
    cudaFuncSetAttribute(gemm_tn<0>, cudaFuncAttributeMaxDynamicSharedMemorySize, SM_GEMM);
    cudaFuncSetAttribute(scores_softmax, cudaFuncAttributeMaxDynamicSharedMemorySize, SM_SCORES);
    cudaFuncSetAttribute(pv_gemm, cudaFuncAttributeMaxDynamicSharedMemorySize, SM_PV);

    float* qg; cudaGetSymbolAddress((void**)&qg, g_q);
    float* kg; cudaGetSymbolAddress((void**)&kg, g_k);
    float* vg; cudaGetSymbolAddress((void**)&vg, g_v);
    float* cg; cudaGetSymbolAddress((void**)&cg, g_ctx);

    dim3 gp(64, 4);
    gemm_tn<1><<<gp, 256, SM_GEMM>>>(x_q, Wq, bq, qg);
    gemm_tn<1><<<gp, 256, SM_GEMM>>>(x_k, Wk, bk, kg);
    gemm_tn<1><<<gp, 256, SM_GEMM>>>(x_v, Wv, bv, vg);

    scores_softmax<<<dim3(NL / 16, NBH), 256, SM_SCORES>>>(qg, kg, msk, attnp);

    pv_gemm<<<dim3(NL / 128, NBH), 256, SM_PV>>>(attnp, vg, cg);

    gemm_tn<0><<<gp, 256, SM_GEMM>>>(cg, Wo, bo, finalp);
}

// round 6
// speedup vs baseline: 1.4840x; 1.4840x over previous
#include <cuda_runtime.h>
#include <cuda_fp16.h>
#include <cstdint>

#define DEVI __device__ __forceinline__

// ---- problem constants ----
#define NB 4
#define NL 2048
#define ND 512
#define NH 8
#define HD 64
#define NBH (NB*NH)

// ---- scratch ----
static __device__ __half g_qh[(size_t)NBH * NL * HD];
static __device__ __half g_kh[(size_t)NBH * NL * HD];
static __device__ __half g_vh[(size_t)NBH * NL * HD];
static __device__ float  g_ctx[(size_t)NB * NL * ND];
static __device__ float  g_final[(size_t)NB * NL * ND];
static __device__ float  g_attn[(size_t)NBH * NL * NL];   // fallback if attn not in d_out

// ---- PTX helpers ----
DEVI uint32_t f2tf(float f) {
    uint32_t u;
    asm volatile("cvt.rna.tf32.f32 %0, %1;" : "=r"(u) : "f"(f));
    return u;
}
DEVI void mma_tf32(float c[4], const uint32_t a[4], const uint32_t b[2]) {
    asm volatile(
        "mma.sync.aligned.m16n8k8.row.col.f32.tf32.tf32.f32 "
        "{%0,%1,%2,%3},{%4,%5,%6,%7},{%8,%9},{%0,%1,%2,%3};"
        : "+f"(c[0]), "+f"(c[1]), "+f"(c[2]), "+f"(c[3])
        : "r"(a[0]), "r"(a[1]), "r"(a[2]), "r"(a[3]), "r"(b[0]), "r"(b[1]));
}
DEVI void mma_f16(float c[4], const uint32_t a[4], const uint32_t b[2]) {
    asm volatile(
        "mma.sync.aligned.m16n8k16.row.col.f32.f16.f16.f32 "
        "{%0,%1,%2,%3},{%4,%5,%6,%7},{%8,%9},{%0,%1,%2,%3};"
        : "+f"(c[0]), "+f"(c[1]), "+f"(c[2]), "+f"(c[3])
        : "r"(a[0]), "r"(a[1]), "r"(a[2]), "r"(a[3]), "r"(b[0]), "r"(b[1]));
}
DEVI void cpa16(void* s, const void* g) {
    uint32_t sa = (uint32_t)__cvta_generic_to_shared(s);
    asm volatile("cp.async.cg.shared.global [%0], [%1], 16;" :: "r"(sa), "l"(g));
}
DEVI void cp_commit() { asm volatile("cp.async.commit_group;"); }
template <int N> DEVI void cp_wait() { asm volatile("cp.async.wait_group %0;" :: "n"(N)); }
DEVI uint32_t packh2(float a, float b) {
    __half2 h = __floats2half2_rn(a, b);
    return *reinterpret_cast<uint32_t*>(&h);
}

// ============================================================================
// TN GEMM: out[m,n] = sum_k A[m,k]*W[n,k] + bias[n].  M=8192,N=512,K=512.
//   PERM=1 (OutT=half): head-split layout [BH, L, 64] fp16 (QKV projections)
//   PERM=0 (OutT=float): row-major [M, 512] fp32      (output projection)
// ============================================================================
template <int PERM, typename OutT>
__global__ __launch_bounds__(256, 1) void gemm_tn(
    const float* __restrict__ A, const float* __restrict__ W,
    const float* __restrict__ bias, OutT* __restrict__ out)
{
    extern __shared__ float sm[];
    float* As = sm;
    float* Bs = sm + 2 * 128 * 36;
    const int tid  = threadIdx.x;
    const int lane = tid & 31, wid = tid >> 5;
    const int wm = wid & 3, wn = wid >> 2;
    const int m0 = blockIdx.x * 128, n0 = blockIdx.y * 128;

    float acc[2][8][4];
#pragma unroll
    for (int i = 0; i < 2; i++)
#pragma unroll
        for (int j = 0; j < 8; j++)
#pragma unroll
            for (int e = 0; e < 4; e++) acc[i][j][e] = 0.f;

    const int lr = tid >> 3, lc = (tid & 7) * 4;
    auto load_tile = [&](int buf, int kt) {
        const float* ag = A + (size_t)m0 * 512 + kt * 32;
        const float* bg = W + (size_t)n0 * 512 + kt * 32;
#pragma unroll
        for (int i = 0; i < 4; i++) {
            int r = lr + 32 * i;
            cpa16(&As[buf * 4608 + r * 36 + lc], ag + (size_t)r * 512 + lc);
            cpa16(&Bs[buf * 4608 + r * 36 + lc], bg + (size_t)r * 512 + lc);
        }
        cp_commit();
    };

    load_tile(0, 0);
    for (int kt = 0; kt < 16; kt++) {
        if (kt < 15) { load_tile((kt + 1) & 1, kt + 1); cp_wait<1>(); }
        else         { cp_wait<0>(); }
        __syncthreads();
        const float* as = &As[(kt & 1) * 4608];
        const float* bs = &Bs[(kt & 1) * 4608];
#pragma unroll
        for (int kk = 0; kk < 4; kk++) {
            int k0 = kk * 8 + (lane & 3);
            uint32_t af[2][4], bf[8][2];
#pragma unroll
            for (int i = 0; i < 2; i++) {
                int m = wm * 32 + i * 16 + (lane >> 2);
                af[i][0] = f2tf(as[m * 36 + k0]);
                af[i][1] = f2tf(as[(m + 8) * 36 + k0]);
                af[i][2] = f2tf(as[m * 36 + k0 + 4]);
                af[i][3] = f2tf(as[(m + 8) * 36 + k0 + 4]);
            }
#pragma unroll
            for (int j = 0; j < 8; j++) {
                int n = wn * 64 + j * 8 + (lane >> 2);
                bf[j][0] = f2tf(bs[n * 36 + k0]);
                bf[j][1] = f2tf(bs[n * 36 + k0 + 4]);
            }
#pragma unroll
            for (int i = 0; i < 2; i++)
#pragma unroll
                for (int j = 0; j < 8; j++) mma_tf32(acc[i][j], af[i], bf[j]);
        }
        __syncthreads();
    }

#pragma unroll
    for (int i = 0; i < 2; i++)
#pragma unroll
        for (int j = 0; j < 8; j++)
#pragma unroll
            for (int e = 0; e < 4; e++) {
                int row = m0 + wm * 32 + i * 16 + (lane >> 2) + ((e >> 1) * 8);
                int col = n0 + wn * 64 + j * 8 + ((lane & 3) * 2) + (e & 1);
                float v = acc[i][j][e] + __ldg(&bias[col]);
                if (PERM) {
                    int bb = row >> 11, l = row & (NL - 1);
                    out[(((size_t)(bb * NH + (col >> 6))) * NL + l) * HD + (col & 63)] = (OutT)v;
                } else {
                    out[(size_t)row * ND + col] = (OutT)v;
                }
            }
}

// ============================================================================
// Fused attention: per CTA 64 q-rows, full L keys in 64-token chunks.
//   Sweep 1: QK^T (fp16 mma) -> exp(s/8 + mask*-1e30) -> row sums l
//   Sweep 2: recompute QK^T -> p = exp(..)/l -> write attn + P.V mma -> ctx
// 8 warps: wq = wid>>1 (16 q-rows each), wk = wid&1 (32-key half of chunk).
// smem: Qs[64][72]h + Ks[2][64][72]h + Vs[2][64][72]h + invl[64] + lpart[128]
//       = 46,848 B  (O reduction reuses the Ks region at the end)
// ============================================================================
__global__ __launch_bounds__(256) void attn_fused(
    const __half* __restrict__ Q, const __half* __restrict__ K,
    const __half* __restrict__ V, const int* __restrict__ mask,
    float* __restrict__ attn, float* __restrict__ ctx)
{
    extern __shared__ __align__(16) __half sh[];
    __half* Qs = sh;                   // 64*72
    __half* Ks = sh + 4608;            // 2 * 64*72
    __half* Vs = sh + 3 * 4608;        // 2 * 64*72
    float* invl  = (float*)(sh + 5 * 4608);  // 64
    float* lpart = invl + 64;                // 2*64

    const int tid = threadIdx.x, lane = tid & 31, wid = tid >> 5;
    const int wq = wid >> 1, wk = wid & 1;
    const int bh = blockIdx.y, b = bh >> 3, h = bh & 7;
    const int q0 = blockIdx.x * 64;

    const __half* Qg = Q + ((size_t)bh * NL + q0) * HD;
    const __half* Kg = K + (size_t)bh * NL * HD;
    const __half* Vg = V + (size_t)bh * NL * HD;
    const int* maskb = mask + (size_t)b * NL * NL;

    const int ldr = tid >> 3, ldc = (tid & 7) * 8;   // 16B per thread, 2 rounds

    auto loadQ = [&]() {
#pragma unroll
        for (int i = 0; i < 2; i++) {
            int r = ldr + 32 * i;
            cpa16(&Qs[r * 72 + ldc], Qg + (size_t)r * HD + ldc);
        }
    };
    auto loadK = [&](int buf, int ch) {
#pragma unroll
        for (int i = 0; i < 2; i++) {
            int r = ldr + 32 * i;
            cpa16(&Ks[buf * 4608 + r * 72 + ldc], Kg + (size_t)(ch * 64 + r) * HD + ldc);
        }
    };
    auto loadV = [&](int buf, int ch) {
#pragma unroll
        for (int i = 0; i < 2; i++) {
            int r = ldr + 32 * i;
            cpa16(&Vs[buf * 4608 + r * 72 + ldc], Vg + (size_t)(ch * 64 + r) * HD + ldc);
        }
    };

    const int rq  = wq * 16 + (lane >> 2);      // local q row (and +8)
    const int r0g = q0 + rq;                    // global q row
    const int kc  = (lane & 3) * 2;

    uint32_t qf[4][4];                          // Q A-frags, reused both sweeps
    float lsum0 = 0.f, lsum1 = 0.f;

    // ---------------- sweep 1: row sums ----------------
    loadQ(); loadK(0, 0); cp_commit();
    for (int ch = 0; ch < 32; ch++) {
        if (ch < 31) { loadK((ch + 1) & 1, ch + 1); cp_commit(); cp_wait<1>(); }
        else         { cp_wait<0>(); }
        __syncthreads();
        if (ch == 0) {
#pragma unroll
            for (int s = 0; s < 4; s++) {
                int k0 = s * 16 + kc;
                qf[s][0] = *(const uint32_t*)&Qs[rq * 72 + k0];
                qf[s][1] = *(const uint32_t*)&Qs[(rq + 8) * 72 + k0];
                qf[s][2] = *(const uint32_t*)&Qs[rq * 72 + k0 + 8];
                qf[s][3] = *(const uint32_t*)&Qs[(rq + 8) * 72 + k0 + 8];
            }
        }
        const __half* ks = &Ks[(ch & 1) * 4608];
#pragma unroll
        for (int j = 0; j < 4; j++) {
            float acc[4] = {0.f, 0.f, 0.f, 0.f};
            const int n = wk * 32 + j * 8 + (lane >> 2);
#pragma unroll
            for (int s = 0; s < 4; s++) {
                uint32_t bb[2];
                int k0 = s * 16 + kc;
                bb[0] = *(const uint32_t*)&ks[n * 72 + k0];
                bb[1] = *(const uint32_t*)&ks[n * 72 + k0 + 8];
                mma_f16(acc, qf[s], bb);
            }
            int colg = ch * 64 + wk * 32 + j * 8 + kc;
            int2 m0 = *(const int2*)&maskb[(size_t)r0g * NL + colg];
            int2 m1 = *(const int2*)&maskb[(size_t)(r0g + 8) * NL + colg];
            lsum0 += __expf(fmaf((float)m0.x, -1e30f, acc[0] * 0.125f))
                   + __expf(fmaf((float)m0.y, -1e30f, acc[1] * 0.125f));
            lsum1 += __expf(fmaf((float)m1.x, -1e30f, acc[2] * 0.125f))
                   + __expf(fmaf((float)m1.y, -1e30f, acc[3] * 0.125f));
        }
        __syncthreads();
    }
    // reduce across the 4 lanes of each row-quad
    lsum0 += __shfl_xor_sync(0xffffffffu, lsum0, 1);
    lsum0 += __shfl_xor_sync(0xffffffffu, lsum0, 2);
    lsum1 += __shfl_xor_sync(0xffffffffu, lsum1, 1);
    lsum1 += __shfl_xor_sync(0xffffffffu, lsum1, 2);
    if ((lane & 3) == 0) {
        lpart[wk * 64 + rq]     = lsum0;
        lpart[wk * 64 + rq + 8] = lsum1;
    }
    __syncthreads();
    if (tid < 64) invl[tid] = 1.0f / (lpart[tid] + lpart[64 + tid]);
    __syncthreads();

    const float il0 = invl[rq], il1 = invl[rq + 8];

    float oacc[8][4];
#pragma unroll
    for (int j = 0; j < 8; j++)
#pragma unroll
        for (int e = 0; e < 4; e++) oacc[j][e] = 0.f;

    // ---------------- sweep 2: attn write + P.V ----------------
    loadK(0, 0); loadV(0, 0); cp_commit();
    for (int ch = 0; ch < 32; ch++) {
        if (ch < 31) { loadK((ch + 1) & 1, ch + 1); loadV((ch + 1) & 1, ch + 1);
                       cp_commit(); cp_wait<1>(); }
        else         { cp_wait<0>(); }
        __syncthreads();
        const __half* ks = &Ks[(ch & 1) * 4608];
        const __half* vs = &Vs[(ch & 1) * 4608];

        uint32_t pa[2][4];
#pragma unroll
        for (int j = 0; j < 4; j++) {
            float acc[4] = {0.f, 0.f, 0.f, 0.f};
            const int n = wk * 32 + j * 8 + (lane >> 2);
#pragma unroll
            for (int s = 0; s < 4; s++) {
                uint32_t bb[2];
                int k0 = s * 16 + kc;
                bb[0] = *(const uint32_t*)&ks[n * 72 + k0];
                bb[1] = *(const uint32_t*)&ks[n * 72 + k0 + 8];
                mma_f16(acc, qf[s], bb);
            }
            int colg = ch * 64 + wk * 32 + j * 8 + kc;
            int2 m0 = *(const int2*)&maskb[(size_t)r0g * NL + colg];
            int2 m1 = *(const int2*)&maskb[(size_t)(r0g + 8) * NL + colg];
            float p0 = __expf(fmaf((float)m0.x, -1e30f, acc[0] * 0.125f)) * il0;
            float p1 = __expf(fmaf((float)m0.y, -1e30f, acc[1] * 0.125f)) * il0;
            float p2 = __expf(fmaf((float)m1.x, -1e30f, acc[2] * 0.125f)) * il1;
            float p3 = __expf(fmaf((float)m1.y, -1e30f, acc[3] * 0.125f)) * il1;
            *(float2*)&attn[((size_t)bh * NL + r0g) * NL + colg]       = make_float2(p0, p1);
            *(float2*)&attn[((size_t)bh * NL + r0g + 8) * NL + colg]   = make_float2(p2, p3);
            int s2 = j >> 1;
            if ((j & 1) == 0) { pa[s2][0] = packh2(p0, p1); pa[s2][1] = packh2(p2, p3); }
            else              { pa[s2][2] = packh2(p0, p1); pa[s2][3] = packh2(p2, p3); }
        }
        // P.V: warp's 32 keys (2 ksteps of 16), 64 d-cols (8 n-frags)
#pragma unroll
        for (int s = 0; s < 2; s++) {
            const int kk = wk * 32 + s * 16 + kc;
#pragma unroll
            for (int jn = 0; jn < 8; jn++) {
                const int dd = jn * 8 + (lane >> 2);
                uint32_t bv[2];
                __half2 h0, h1;
                h0.x = vs[kk * 72 + dd];       h0.y = vs[(kk + 1) * 72 + dd];
                h1.x = vs[(kk + 8) * 72 + dd]; h1.y = vs[(kk + 9) * 72 + dd];
                bv[0] = *reinterpret_cast<uint32_t*>(&h0);
                bv[1] = *reinterpret_cast<uint32_t*>(&h1);
                mma_f16(oacc[jn], pa[s], bv);
            }
        }
        __syncthreads();
    }

    // ---------------- O reduction (wk pair) + ctx store ----------------
    float* osum = (float*)Ks;   // 64 x 72 f32 = 18432 B, fits in Ks region
    if (wk == 1) {
#pragma unroll
        for (int jn = 0; jn < 8; jn++)
#pragma unroll
            for (int e = 0; e < 4; e++) {
                int row = wq * 16 + (lane >> 2) + (e >> 1) * 8;
                int col = jn * 8 + kc + (e & 1);
                osum[row * 72 + col] = oacc[jn][e];
            }
    }
    __syncthreads();
    if (wk == 0) {
#pragma unroll
        for (int jn = 0; jn < 8; jn++)
#pragma unroll
            for (int e = 0; e < 4; e++) {
                int row = wq * 16 + (lane >> 2) + (e >> 1) * 8;
                int col = jn * 8 + kc + (e & 1);
                osum[row * 72 + col] += oacc[jn][e];
            }
    }
    __syncthreads();
    for (int i = tid; i < 64 * 16; i += 256) {
        int row = i >> 4, c4 = (i & 15) * 4;
        float4 v = *(const float4*)&osum[row * 72 + c4];
        *(float4*)&ctx[((size_t)b * NL + q0 + row) * ND + h * HD + c4] = v;
    }
}

// ============================================================================
// launch
// ============================================================================
extern "C" void kernel_launch(void* const* d_in, const int* in_sizes, int n_in,
                              void* d_out, int out_size) {
    (void)in_sizes; (void)n_in;
    const float* x_q = (const float*)d_in[0];
    const float* x_k = (const float*)d_in[1];
    const float* x_v = (const float*)d_in[2];
    const int*   msk = (const int*)d_in[3];
    const float* Wq  = (const float*)d_in[4];
    const float* bq  = (const float*)d_in[5];
    const float* Wk  = (const float*)d_in[6];
    const float* bk  = (const float*)d_in[7];
    const float* Wv  = (const float*)d_in[8];
    const float* bv  = (const float*)d_in[9];
    const float* Wo  = (const float*)d_in[10];
    const float* bo  = (const float*)d_in[11];

    const long long FINAL_N = (long long)NB * NL * ND;
    const long long ATTN_N  = (long long)NBH * NL * NL;

    float* outp = (float*)d_out;
    float *finalp, *attnp;
    if ((long long)out_size >= FINAL_N + ATTN_N) { finalp = outp; attnp = outp + FINAL_N; }
    else if ((long long)out_size == ATTN_N)      { attnp = outp;  finalp = g_final; }
    else                                         { finalp = outp; attnp = g_attn; }

    const int SM_GEMM = 2 * (2 * 128 * 36) * 4;                    // 73,728 B
    const int SM_ATTN = 5 * 4608 * 2 + (64 + 128) * 4;             // 46,848 B

    cudaFuncSetAttribute(gemm_tn<1, __half>, cudaFuncAttributeMaxDynamicSharedMemorySize, SM_GEMM);
    cudaFuncSetAttribute(gemm_tn<0, float>,  cudaFuncAttributeMaxDynamicSharedMemorySize, SM_GEMM);
    cudaFuncSetAttribute(attn_fused, cudaFuncAttributeMaxDynamicSharedMemorySize, SM_ATTN);

    __half* qg; cudaGetSymbolAddress((void**)&qg, g_qh);
    __half* kg; cudaGetSymbolAddress((void**)&kg, g_kh);
    __half* vg; cudaGetSymbolAddress((void**)&vg, g_vh);
    float*  cg; cudaGetSymbolAddress((void**)&cg, g_ctx);

    dim3 gp(64, 4);
    gemm_tn<1, __half><<<gp, 256, SM_GEMM>>>(x_q, Wq, bq, qg);
    gemm_tn<1, __half><<<gp, 256, SM_GEMM>>>(x_k, Wk, bk, kg);
    gemm_tn<1, __half><<<gp, 256, SM_GEMM>>>(x_v, Wv, bv, vg);

    attn_fused<<<dim3(NL / 64, NBH), 256, SM_ATTN>>>(qg, kg, vg, msk, attnp, cg);

    gemm_tn<0, float><<<gp, 256, SM_GEMM>>>(cg, Wo, bo, finalp);
}

// round 7
// speedup vs baseline: 1.7684x; 1.1917x over previous
#include <cuda_runtime.h>
#include <cuda_fp16.h>
#include <cstdint>

#define DEVI __device__ __forceinline__

// ---- problem constants ----
#define NB 4
#define NL 2048
#define ND 512
#define NH 8
#define HD 64
#define NBH (NB*NH)

// ---- scratch ----
static __device__ __half g_qh[(size_t)NBH * NL * HD];
static __device__ __half g_kh[(size_t)NBH * NL * HD];
static __device__ __half g_vh[(size_t)NBH * NL * HD];
static __device__ float  g_ctx[(size_t)NB * NL * ND];
static __device__ float  g_final[(size_t)NB * NL * ND];
static __device__ float  g_attn[(size_t)NBH * NL * NL];   // fallback if attn not in d_out

// ---- PTX helpers ----
DEVI uint32_t f2tf(float f) {
    uint32_t u;
    asm volatile("cvt.rna.tf32.f32 %0, %1;" : "=r"(u) : "f"(f));
    return u;
}
DEVI void mma_tf32(float c[4], const uint32_t a[4], const uint32_t b[2]) {
    asm volatile(
        "mma.sync.aligned.m16n8k8.row.col.f32.tf32.tf32.f32 "
        "{%0,%1,%2,%3},{%4,%5,%6,%7},{%8,%9},{%0,%1,%2,%3};"
        : "+f"(c[0]), "+f"(c[1]), "+f"(c[2]), "+f"(c[3])
        : "r"(a[0]), "r"(a[1]), "r"(a[2]), "r"(a[3]), "r"(b[0]), "r"(b[1]));
}
DEVI void mma_f16(float c[4], const uint32_t a[4], const uint32_t b[2]) {
    asm volatile(
        "mma.sync.aligned.m16n8k16.row.col.f32.f16.f16.f32 "
        "{%0,%1,%2,%3},{%4,%5,%6,%7},{%8,%9},{%0,%1,%2,%3};"
        : "+f"(c[0]), "+f"(c[1]), "+f"(c[2]), "+f"(c[3])
        : "r"(a[0]), "r"(a[1]), "r"(a[2]), "r"(a[3]), "r"(b[0]), "r"(b[1]));
}
DEVI void ldsm_x4(uint32_t r[4], uint32_t addr) {
    asm volatile("ldmatrix.sync.aligned.m8n8.x4.shared.b16 {%0,%1,%2,%3}, [%4];"
        : "=r"(r[0]), "=r"(r[1]), "=r"(r[2]), "=r"(r[3]) : "r"(addr));
}
DEVI void ldsm_x4_t(uint32_t r[4], uint32_t addr) {
    asm volatile("ldmatrix.sync.aligned.m8n8.x4.trans.shared.b16 {%0,%1,%2,%3}, [%4];"
        : "=r"(r[0]), "=r"(r[1]), "=r"(r[2]), "=r"(r[3]) : "r"(addr));
}
DEVI void cpa16(void* s, const void* g) {
    uint32_t sa = (uint32_t)__cvta_generic_to_shared(s);
    asm volatile("cp.async.cg.shared.global [%0], [%1], 16;" :: "r"(sa), "l"(g));
}
DEVI void cp_commit() { asm volatile("cp.async.commit_group;"); }
template <int N> DEVI void cp_wait() { asm volatile("cp.async.wait_group %0;" :: "n"(N)); }
DEVI uint32_t packh2(float a, float b) {
    __half2 h = __floats2half2_rn(a, b);
    return *reinterpret_cast<uint32_t*>(&h);
}

// ============================================================================
// TN GEMM: out[m,n] = sum_k A[m,k]*W[n,k] + bias[n].  M=8192,N=512,K=512.
//   PERM=1 (OutT=half): head-split layout [BH, L, 64] fp16 (QKV projections)
//   PERM=0 (OutT=float): row-major [M, 512] fp32      (output projection)
// ============================================================================
template <int PERM, typename OutT>
__global__ __launch_bounds__(256, 1) void gemm_tn(
    const float* __restrict__ A, const float* __restrict__ W,
    const float* __restrict__ bias, OutT* __restrict__ out)
{
    extern __shared__ float sm[];
    float* As = sm;
    float* Bs = sm + 2 * 128 * 36;
    const int tid  = threadIdx.x;
    const int lane = tid & 31, wid = tid >> 5;
    const int wm = wid & 3, wn = wid >> 2;
    const int m0 = blockIdx.x * 128, n0 = blockIdx.y * 128;

    float acc[2][8][4];
#pragma unroll
    for (int i = 0; i < 2; i++)
#pragma unroll
        for (int j = 0; j < 8; j++)
#pragma unroll
            for (int e = 0; e < 4; e++) acc[i][j][e] = 0.f;

    const int lr = tid >> 3, lc = (tid & 7) * 4;
    auto load_tile = [&](int buf, int kt) {
        const float* ag = A + (size_t)m0 * 512 + kt * 32;
        const float* bg = W + (size_t)n0 * 512 + kt * 32;
#pragma unroll
        for (int i = 0; i < 4; i++) {
            int r = lr + 32 * i;
            cpa16(&As[buf * 4608 + r * 36 + lc], ag + (size_t)r * 512 + lc);
            cpa16(&Bs[buf * 4608 + r * 36 + lc], bg + (size_t)r * 512 + lc);
        }
        cp_commit();
    };

    load_tile(0, 0);
    for (int kt = 0; kt < 16; kt++) {
        if (kt < 15) { load_tile((kt + 1) & 1, kt + 1); cp_wait<1>(); }
        else         { cp_wait<0>(); }
        __syncthreads();
        const float* as = &As[(kt & 1) * 4608];
        const float* bs = &Bs[(kt & 1) * 4608];
#pragma unroll
        for (int kk = 0; kk < 4; kk++) {
            int k0 = kk * 8 + (lane & 3);
            uint32_t af[2][4], bf[8][2];
#pragma unroll
            for (int i = 0; i < 2; i++) {
                int m = wm * 32 + i * 16 + (lane >> 2);
                af[i][0] = f2tf(as[m * 36 + k0]);
                af[i][1] = f2tf(as[(m + 8) * 36 + k0]);
                af[i][2] = f2tf(as[m * 36 + k0 + 4]);
                af[i][3] = f2tf(as[(m + 8) * 36 + k0 + 4]);
            }
#pragma unroll
            for (int j = 0; j < 8; j++) {
                int n = wn * 64 + j * 8 + (lane >> 2);
                bf[j][0] = f2tf(bs[n * 36 + k0]);
                bf[j][1] = f2tf(bs[n * 36 + k0 + 4]);
            }
#pragma unroll
            for (int i = 0; i < 2; i++)
#pragma unroll
                for (int j = 0; j < 8; j++) mma_tf32(acc[i][j], af[i], bf[j]);
        }
        __syncthreads();
    }

#pragma unroll
    for (int i = 0; i < 2; i++)
#pragma unroll
        for (int j = 0; j < 8; j++)
#pragma unroll
            for (int e = 0; e < 4; e++) {
                int row = m0 + wm * 32 + i * 16 + (lane >> 2) + ((e >> 1) * 8);
                int col = n0 + wn * 64 + j * 8 + ((lane & 3) * 2) + (e & 1);
                float v = acc[i][j][e] + __ldg(&bias[col]);
                if (PERM) {
                    int bb = row >> 11, l = row & (NL - 1);
                    out[(((size_t)(bb * NH + (col >> 6))) * NL + l) * HD + (col & 63)] = (OutT)v;
                } else {
                    out[(size_t)row * ND + col] = (OutT)v;
                }
            }
}

// ============================================================================
// Fused attention (ldmatrix version): per CTA 64 q-rows, full L in 64-key chunks.
//   Sweep 1: QK^T (ldmatrix B-frags) -> exp (mask-select) -> row sums l
//   Sweep 2: recompute QK^T -> p=exp*il -> attn write + P.V (ldmatrix.trans V)
// 8 warps: wq = wid>>1 (16 q-rows), wk = wid&1 (32-key half of chunk).
// smem: Qs[64][72]h + Ks[2][64][72]h + Vs[2][64][72]h + invl[64] + lpart[128]
// ============================================================================
__global__ __launch_bounds__(256, 2) void attn_fused(
    const __half* __restrict__ Q, const __half* __restrict__ K,
    const __half* __restrict__ V, const int* __restrict__ mask,
    float* __restrict__ attn, float* __restrict__ ctx)
{
    extern __shared__ __align__(16) __half sh[];
    __half* Qs = sh;                   // 64*72
    __half* Ks = sh + 4608;            // 2 * 64*72
    __half* Vs = sh + 3 * 4608;        // 2 * 64*72
    float* invl  = (float*)(sh + 5 * 4608);  // 64
    float* lpart = invl + 64;                // 2*64

    const int tid = threadIdx.x, lane = tid & 31, wid = tid >> 5;
    const int wq = wid >> 1, wk = wid & 1;
    const int bh = blockIdx.y, b = bh >> 3, h = bh & 7;
    const int q0 = blockIdx.x * 64;

    const __half* Qg = Q + ((size_t)bh * NL + q0) * HD;
    const __half* Kg = K + (size_t)bh * NL * HD;
    const __half* Vg = V + (size_t)bh * NL * HD;
    const int* maskb = mask + (size_t)b * NL * NL;

    const uint32_t shb = (uint32_t)__cvta_generic_to_shared(sh);
    // ldmatrix per-lane byte offsets (within the Ks/Vs buffer)
    // K (non-trans): tile t = lane>>3; row n = wk*32 + (t>>1)*8 + (lane&7) (+jp*16),
    //                col k = (t&1)*8 (+s*16)
    const uint32_t k_loff =
        ((uint32_t)(wk * 32 + ((lane >> 4) << 3) + (lane & 7)) * 72 +
         (((lane >> 3) & 1) << 3)) * 2;
    // V (trans): row k = wk*32 + (t&1)*8 + (lane&7) (+s2*16), col n = (t>>1)*8 (+jnp*16)
    const uint32_t v_loff =
        ((uint32_t)(wk * 32 + (((lane >> 3) & 1) << 3) + (lane & 7)) * 72 +
         ((lane >> 4) << 3)) * 2;

    const int ldr = tid >> 3, ldc = (tid & 7) * 8;   // 16B per thread, 2 rounds

    auto loadQ = [&]() {
#pragma unroll
        for (int i = 0; i < 2; i++) {
            int r = ldr + 32 * i;
            cpa16(&Qs[r * 72 + ldc], Qg + (size_t)r * HD + ldc);
        }
    };
    auto loadK = [&](int buf, int ch) {
#pragma unroll
        for (int i = 0; i < 2; i++) {
            int r = ldr + 32 * i;
            cpa16(&Ks[buf * 4608 + r * 72 + ldc], Kg + (size_t)(ch * 64 + r) * HD + ldc);
        }
    };
    auto loadV = [&](int buf, int ch) {
#pragma unroll
        for (int i = 0; i < 2; i++) {
            int r = ldr + 32 * i;
            cpa16(&Vs[buf * 4608 + r * 72 + ldc], Vg + (size_t)(ch * 64 + r) * HD + ldc);
        }
    };

    const int rq  = wq * 16 + (lane >> 2);      // local q row (and +8)
    const int r0g = q0 + rq;                    // global q row
    const int kc  = (lane & 3) * 2;

    uint32_t qf[4][4];                          // Q A-frags, reused both sweeps
    float lsum0 = 0.f, lsum1 = 0.f;

    // ---------------- sweep 1: row sums ----------------
    loadQ(); loadK(0, 0); cp_commit();
    for (int ch = 0; ch < 32; ch++) {
        if (ch < 31) { loadK((ch + 1) & 1, ch + 1); cp_commit(); cp_wait<1>(); }
        else         { cp_wait<0>(); }
        __syncthreads();
        if (ch == 0) {
#pragma unroll
            for (int s = 0; s < 4; s++) {
                int k0 = s * 16 + kc;
                qf[s][0] = *(const uint32_t*)&Qs[rq * 72 + k0];
                qf[s][1] = *(const uint32_t*)&Qs[(rq + 8) * 72 + k0];
                qf[s][2] = *(const uint32_t*)&Qs[rq * 72 + k0 + 8];
                qf[s][3] = *(const uint32_t*)&Qs[(rq + 8) * 72 + k0 + 8];
            }
        }
        const uint32_t ksb = shb + (uint32_t)(4608 + (ch & 1) * 4608) * 2 + k_loff;

        float acc[4][4];
#pragma unroll
        for (int j = 0; j < 4; j++)
#pragma unroll
            for (int e = 0; e < 4; e++) acc[j][e] = 0.f;
#pragma unroll
        for (int jp = 0; jp < 2; jp++)
#pragma unroll
            for (int s = 0; s < 4; s++) {
                uint32_t r[4];
                ldsm_x4(r, ksb + (uint32_t)(jp * 16 * 72 + s * 16) * 2);
                mma_f16(acc[2 * jp],     qf[s], &r[0]);
                mma_f16(acc[2 * jp + 1], qf[s], &r[2]);
            }
#pragma unroll
        for (int j = 0; j < 4; j++) {
            int colg = ch * 64 + wk * 32 + j * 8 + kc;
            int2 m0 = *(const int2*)&maskb[(size_t)r0g * NL + colg];
            int2 m1 = *(const int2*)&maskb[(size_t)(r0g + 8) * NL + colg];
            float e0 = __expf(acc[j][0] * 0.125f);
            float e1 = __expf(acc[j][1] * 0.125f);
            float e2 = __expf(acc[j][2] * 0.125f);
            float e3 = __expf(acc[j][3] * 0.125f);
            lsum0 += (m0.x ? 0.f : e0) + (m0.y ? 0.f : e1);
            lsum1 += (m1.x ? 0.f : e2) + (m1.y ? 0.f : e3);
        }
        __syncthreads();
    }
    // reduce across the 4 lanes of each row-quad
    lsum0 += __shfl_xor_sync(0xffffffffu, lsum0, 1);
    lsum0 += __shfl_xor_sync(0xffffffffu, lsum0, 2);
    lsum1 += __shfl_xor_sync(0xffffffffu, lsum1, 1);
    lsum1 += __shfl_xor_sync(0xffffffffu, lsum1, 2);
    if ((lane & 3) == 0) {
        lpart[wk * 64 + rq]     = lsum0;
        lpart[wk * 64 + rq + 8] = lsum1;
    }
    __syncthreads();
    if (tid < 64) invl[tid] = 1.0f / (lpart[tid] + lpart[64 + tid]);
    __syncthreads();

    const float il0 = invl[rq], il1 = invl[rq + 8];

    float oacc[8][4];
#pragma unroll
    for (int j = 0; j < 8; j++)
#pragma unroll
        for (int e = 0; e < 4; e++) oacc[j][e] = 0.f;

    // ---------------- sweep 2: attn write + P.V ----------------
    loadK(0, 0); loadV(0, 0); cp_commit();
    for (int ch = 0; ch < 32; ch++) {
        if (ch < 31) { loadK((ch + 1) & 1, ch + 1); loadV((ch + 1) & 1, ch + 1);
                       cp_commit(); cp_wait<1>(); }
        else         { cp_wait<0>(); }
        __syncthreads();
        const uint32_t ksb = shb + (uint32_t)(4608 + (ch & 1) * 4608) * 2 + k_loff;
        const uint32_t vsb = shb + (uint32_t)(3 * 4608 + (ch & 1) * 4608) * 2 + v_loff;

        float acc[4][4];
#pragma unroll
        for (int j = 0; j < 4; j++)
#pragma unroll
            for (int e = 0; e < 4; e++) acc[j][e] = 0.f;
#pragma unroll
        for (int jp = 0; jp < 2; jp++)
#pragma unroll
            for (int s = 0; s < 4; s++) {
                uint32_t r[4];
                ldsm_x4(r, ksb + (uint32_t)(jp * 16 * 72 + s * 16) * 2);
                mma_f16(acc[2 * jp],     qf[s], &r[0]);
                mma_f16(acc[2 * jp + 1], qf[s], &r[2]);
            }

        uint32_t pa[2][4];
#pragma unroll
        for (int j = 0; j < 4; j++) {
            int colg = ch * 64 + wk * 32 + j * 8 + kc;
            int2 m0 = *(const int2*)&maskb[(size_t)r0g * NL + colg];
            int2 m1 = *(const int2*)&maskb[(size_t)(r0g + 8) * NL + colg];
            float e0 = __expf(acc[j][0] * 0.125f);
            float e1 = __expf(acc[j][1] * 0.125f);
            float e2 = __expf(acc[j][2] * 0.125f);
            float e3 = __expf(acc[j][3] * 0.125f);
            float p0 = (m0.x ? 0.f : e0) * il0;
            float p1 = (m0.y ? 0.f : e1) * il0;
            float p2 = (m1.x ? 0.f : e2) * il1;
            float p3 = (m1.y ? 0.f : e3) * il1;
            *(float2*)&attn[((size_t)bh * NL + r0g) * NL + colg]     = make_float2(p0, p1);
            *(float2*)&attn[((size_t)bh * NL + r0g + 8) * NL + colg] = make_float2(p2, p3);
            int s2 = j >> 1;
            if ((j & 1) == 0) { pa[s2][0] = packh2(p0, p1); pa[s2][1] = packh2(p2, p3); }
            else              { pa[s2][2] = packh2(p0, p1); pa[s2][3] = packh2(p2, p3); }
        }
        // P.V: warp's 32 keys (2 ksteps of 16), 64 d-cols via ldmatrix.trans
#pragma unroll
        for (int s2 = 0; s2 < 2; s2++)
#pragma unroll
            for (int jnp = 0; jnp < 4; jnp++) {
                uint32_t r[4];
                ldsm_x4_t(r, vsb + (uint32_t)(s2 * 16 * 72 + jnp * 16) * 2);
                mma_f16(oacc[2 * jnp],     pa[s2], &r[0]);
                mma_f16(oacc[2 * jnp + 1], pa[s2], &r[2]);
            }
        __syncthreads();
    }

    // ---------------- O reduction (wk pair) + ctx store ----------------
    float* osum = (float*)Ks;   // 64 x 72 f32 = 18432 B, fits in Ks region
    if (wk == 1) {
#pragma unroll
        for (int jn = 0; jn < 8; jn++)
#pragma unroll
            for (int e = 0; e < 4; e++) {
                int row = wq * 16 + (lane >> 2) + (e >> 1) * 8;
                int col = jn * 8 + kc + (e & 1);
                osum[row * 72 + col] = oacc[jn][e];
            }
    }
    __syncthreads();
    if (wk == 0) {
#pragma unroll
        for (int jn = 0; jn < 8; jn++)
#pragma unroll
            for (int e = 0; e < 4; e++) {
                int row = wq * 16 + (lane >> 2) + (e >> 1) * 8;
                int col = jn * 8 + kc + (e & 1);
                osum[row * 72 + col] += oacc[jn][e];
            }
    }
    __syncthreads();
    for (int i = tid; i < 64 * 16; i += 256) {
        int row = i >> 4, c4 = (i & 15) * 4;
        float4 v = *(const float4*)&osum[row * 72 + c4];
        *(float4*)&ctx[((size_t)b * NL + q0 + row) * ND + h * HD + c4] = v;
    }
}

// ============================================================================
// launch
// ============================================================================
extern "C" void kernel_launch(void* const* d_in, const int* in_sizes, int n_in,
                              void* d_out, int out_size) {
    (void)in_sizes; (void)n_in;
    const float* x_q = (const float*)d_in[0];
    const float* x_k = (const float*)d_in[1];
    const float* x_v = (const float*)d_in[2];
    const int*   msk = (const int*)d_in[3];
    const float* Wq  = (const float*)d_in[4];
    const float* bq  = (const float*)d_in[5];
    const float* Wk  = (const float*)d_in[6];
    const float* bk  = (const float*)d_in[7];
    const float* Wv  = (const float*)d_in[8];
    const float* bv  = (const float*)d_in[9];
    const float* Wo  = (const float*)d_in[10];
    const float* bo  = (const float*)d_in[11];

    const long long FINAL_N = (long long)NB * NL * ND;
    const long long ATTN_N  = (long long)NBH * NL * NL;

    float* outp = (float*)d_out;
    float *finalp, *attnp;
    if ((long long)out_size >= FINAL_N + ATTN_N) { finalp = outp; attnp = outp + FINAL_N; }
    else if ((long long)out_size == ATTN_N)      { attnp = outp;  finalp = g_final; }
    else                                         { finalp = outp; attnp = g_attn; }

    const int SM_GEMM = 2 * (2 * 128 * 36) * 4;                    // 73,728 B
    const int SM_ATTN = 5 * 4608 * 2 + (64 + 128) * 4;             // 46,848 B

    cudaFuncSetAttribute(gemm_tn<1, __half>, cudaFuncAttributeMaxDynamicSharedMemorySize, SM_GEMM);
    cudaFuncSetAttribute(gemm_tn<0, float>,  cudaFuncAttributeMaxDynamicSharedMemorySize, SM_GEMM);
    cudaFuncSetAttribute(attn_fused, cudaFuncAttributeMaxDynamicSharedMemorySize, SM_ATTN);

    __half* qg; cudaGetSymbolAddress((void**)&qg, g_qh);
    __half* kg; cudaGetSymbolAddress((void**)&kg, g_kh);
    __half* vg; cudaGetSymbolAddress((void**)&vg, g_vh);
    float*  cg; cudaGetSymbolAddress((void**)&cg, g_ctx);

    dim3 gp(64, 4);
    gemm_tn<1, __half><<<gp, 256, SM_GEMM>>>(x_q, Wq, bq, qg);
    gemm_tn<1, __half><<<gp, 256, SM_GEMM>>>(x_k, Wk, bk, kg);
    gemm_tn<1, __half><<<gp, 256, SM_GEMM>>>(x_v, Wv, bv, vg);

    attn_fused<<<dim3(NL / 64, NBH), 256, SM_ATTN>>>(qg, kg, vg, msk, attnp, cg);

    gemm_tn<0, float><<<gp, 256, SM_GEMM>>>(cg, Wo, bo, finalp);
}

// round 12
// speedup vs baseline: 1.8584x; 1.0509x over previous
#include <cuda_runtime.h>
#include <cuda_fp16.h>
#include <cstdint>

#define DEVI __device__ __forceinline__

// ---- problem constants ----
#define NB 4
#define NL 2048
#define ND 512
#define NH 8
#define HD 64
#define NBH (NB*NH)

// ---- scratch ----
static __device__ __half g_qh[(size_t)NBH * NL * HD];
static __device__ __half g_kh[(size_t)NBH * NL * HD];
static __device__ __half g_vh[(size_t)NBH * NL * HD];
static __device__ __half g_xh[3][(size_t)NB * NL * ND];     // fp16 x_q, x_k, x_v
static __device__ __half g_wh[4][(size_t)ND * ND];          // fp16 Wq, Wk, Wv, Wo
static __device__ __half g_mb[(size_t)NB * NL * NL];        // fp16 mask bias (0 / -60000)
static __device__ __half g_ctxh[(size_t)NB * NL * ND];
static __device__ float  g_final[(size_t)NB * NL * ND];
static __device__ float  g_attn[(size_t)NBH * NL * NL];     // fallback if attn not in d_out

// ---- PTX helpers ----
DEVI void mma_f16(float c[4], const uint32_t a[4], const uint32_t b[2]) {
    asm volatile(
        "mma.sync.aligned.m16n8k16.row.col.f32.f16.f16.f32 "
        "{%0,%1,%2,%3},{%4,%5,%6,%7},{%8,%9},{%0,%1,%2,%3};"
        : "+f"(c[0]), "+f"(c[1]), "+f"(c[2]), "+f"(c[3])
        : "r"(a[0]), "r"(a[1]), "r"(a[2]), "r"(a[3]), "r"(b[0]), "r"(b[1]));
}
DEVI void ldsm_x4(uint32_t r[4], uint32_t addr) {
    asm volatile("ldmatrix.sync.aligned.m8n8.x4.shared.b16 {%0,%1,%2,%3}, [%4];"
        : "=r"(r[0]), "=r"(r[1]), "=r"(r[2]), "=r"(r[3]) : "r"(addr));
}
DEVI void ldsm_x4_t(uint32_t r[4], uint32_t addr) {
    asm volatile("ldmatrix.sync.aligned.m8n8.x4.trans.shared.b16 {%0,%1,%2,%3}, [%4];"
        : "=r"(r[0]), "=r"(r[1]), "=r"(r[2]), "=r"(r[3]) : "r"(addr));
}
DEVI void cpa16(void* s, const void* g) {
    uint32_t sa = (uint32_t)__cvta_generic_to_shared(s);
    asm volatile("cp.async.cg.shared.global [%0], [%1], 16;" :: "r"(sa), "l"(g));
}
DEVI void cp_commit() { asm volatile("cp.async.commit_group;"); }
template <int N> DEVI void cp_wait() { asm volatile("cp.async.wait_group %0;" :: "n"(N)); }
DEVI uint32_t packh2(float a, float b) {
    __half2 h = __floats2half2_rn(a, b);
    return *reinterpret_cast<uint32_t*>(&h);
}

// ============================================================================
// conversion kernels (one-time per launch, streaming)
// ============================================================================
__global__ void cvt_f16(const float4* __restrict__ in, uint2* __restrict__ out, int n4) {
    int i = blockIdx.x * blockDim.x + threadIdx.x;
    if (i < n4) {
        float4 v = in[i];
        out[i] = make_uint2(packh2(v.x, v.y), packh2(v.z, v.w));
    }
}
__global__ void cvt_maskbias(const int4* __restrict__ in, uint2* __restrict__ out, int n4) {
    int i = blockIdx.x * blockDim.x + threadIdx.x;
    if (i < n4) {
        int4 m = in[i];
        out[i] = make_uint2(
            packh2(m.x ? -60000.f : 0.f, m.y ? -60000.f : 0.f),
            packh2(m.z ? -60000.f : 0.f, m.w ? -60000.f : 0.f));
    }
}

// ============================================================================
// fp16 TN GEMM: out[m,n] = sum_k A[m,k]*W[n,k] + bias[n].  M=8192,N=512,K=512.
//   PERM=1 (OutT=half): head-split layout [BH, L, 64] fp16 (QKV projections)
//   PERM=0 (OutT=float): row-major [M, 512] fp32      (output projection)
// BM=128,BN=128,BK=32, 256 thr (8 warps, warp 32x64), ldmatrix + m16n8k16.
// smem: As/Bs [2][128][40]h = 40,960 B (stride 40h conflict-free for ldsm)
// FIX vs R10: load_tile now issues 2 cp.async per thread per array (full
// 512-chunk coverage of the 128x32 tile; R10 left half of smem unwritten).
// ============================================================================
template <int PERM, typename OutT>
__global__ __launch_bounds__(256, 2) void gemm16(
    const __half* __restrict__ A, const __half* __restrict__ W,
    const float* __restrict__ bias, OutT* __restrict__ out)
{
    extern __shared__ __align__(16) __half smh[];
    __half* As = smh;             // [2][128*40]
    __half* Bs = smh + 2 * 5120;  // [2][128*40]
    const int tid = threadIdx.x, lane = tid & 31, wid = tid >> 5;
    const int wm = wid & 3, wn = wid >> 2;
    const int m0 = blockIdx.x * 128, n0 = blockIdx.y * 128;
    const uint32_t shb = (uint32_t)__cvta_generic_to_shared(smh);

    float acc[2][8][4];
#pragma unroll
    for (int i = 0; i < 2; i++)
#pragma unroll
        for (int j = 0; j < 8; j++)
#pragma unroll
            for (int e = 0; e < 4; e++) acc[i][j][e] = 0.f;

    const int lr = tid >> 1, lc = (tid & 1) * 16;
    auto load_tile = [&](int buf, int kt) {
        const __half* ag = A + (size_t)(m0 + lr) * 512 + kt * 32 + lc;
        const __half* bg = W + (size_t)(n0 + lr) * 512 + kt * 32 + lc;
        __half* as = &As[buf * 5120 + lr * 40 + lc];
        __half* bs = &Bs[buf * 5120 + lr * 40 + lc];
        cpa16(as,     ag);
        cpa16(as + 8, ag + 8);
        cpa16(bs,     bg);
        cpa16(bs + 8, bg + 8);
        cp_commit();
    };
    // ldmatrix lane offsets (bytes)
    const uint32_t a_loff =
        ((uint32_t)((lane & 7) + ((lane >> 3) & 1) * 8) * 40 + (lane >> 4) * 8) * 2;
    const uint32_t b_loff =
        ((uint32_t)((lane & 7) + ((lane >> 4) << 3)) * 40 + ((lane >> 3) & 1) * 8) * 2;

    load_tile(0, 0);
    for (int kt = 0; kt < 16; kt++) {
        if (kt < 15) { load_tile((kt + 1) & 1, kt + 1); cp_wait<1>(); }
        else         { cp_wait<0>(); }
        __syncthreads();
        const uint32_t abase = shb + (uint32_t)((kt & 1) * 5120) * 2 + a_loff;
        const uint32_t bbase = shb + (uint32_t)(2 * 5120 + (kt & 1) * 5120) * 2 + b_loff;
#pragma unroll
        for (int ks = 0; ks < 2; ks++) {
            uint32_t af[2][4], bf[4][4];
#pragma unroll
            for (int mi = 0; mi < 2; mi++)
                ldsm_x4(af[mi], abase + (uint32_t)((wm * 32 + mi * 16) * 40 + ks * 16) * 2);
#pragma unroll
            for (int jn = 0; jn < 4; jn++)
                ldsm_x4(bf[jn], bbase + (uint32_t)((wn * 64 + jn * 16) * 40 + ks * 16) * 2);
#pragma unroll
            for (int mi = 0; mi < 2; mi++)
#pragma unroll
                for (int jn = 0; jn < 4; jn++) {
                    mma_f16(acc[mi][2 * jn],     af[mi], &bf[jn][0]);
                    mma_f16(acc[mi][2 * jn + 1], af[mi], &bf[jn][2]);
                }
        }
        __syncthreads();
    }

#pragma unroll
    for (int i = 0; i < 2; i++)
#pragma unroll
        for (int j = 0; j < 8; j++)
#pragma unroll
            for (int e = 0; e < 4; e++) {
                int row = m0 + wm * 32 + i * 16 + (lane >> 2) + ((e >> 1) * 8);
                int col = n0 + wn * 64 + j * 8 + ((lane & 3) * 2) + (e & 1);
                float v = acc[i][j][e] + __ldg(&bias[col]);
                if (PERM) {
                    int bb = row >> 11, l = row & (NL - 1);
                    out[(((size_t)(bb * NH + (col >> 6))) * NL + l) * HD + (col & 63)] = (OutT)v;
                } else {
                    out[(size_t)row * ND + col] = (OutT)v;
                }
            }
}

// ============================================================================
// Fused attention: per CTA 64 q-rows, full L in 64-key chunks (fp16, ldmatrix).
//   Sweep 1: QK^T -> exp(s/8 + bias) -> row sums l
//   Sweep 2: recompute QK^T -> p = exp*il -> attn write + P.V -> ctx (fp16)
// 8 warps: wq = wid>>1 (16 q-rows), wk = wid&1 (32-key half of chunk).
// ============================================================================
__global__ __launch_bounds__(256, 2) void attn_fused(
    const __half* __restrict__ Q, const __half* __restrict__ K,
    const __half* __restrict__ V, const __half* __restrict__ mbias,
    float* __restrict__ attn, __half* __restrict__ ctx)
{
    extern __shared__ __align__(16) __half sh[];
    __half* Qs = sh;                   // 64*72
    __half* Ks = sh + 4608;            // 2 * 64*72
    __half* Vs = sh + 3 * 4608;        // 2 * 64*72
    float* invl  = (float*)(sh + 5 * 4608);  // 64
    float* lpart = invl + 64;                // 2*64

    const int tid = threadIdx.x, lane = tid & 31, wid = tid >> 5;
    const int wq = wid >> 1, wk = wid & 1;
    const int bh = blockIdx.y, b = bh >> 3, h = bh & 7;
    const int q0 = blockIdx.x * 64;

    const __half* Qg = Q + ((size_t)bh * NL + q0) * HD;
    const __half* Kg = K + (size_t)bh * NL * HD;
    const __half* Vg = V + (size_t)bh * NL * HD;
    const __half* mbb = mbias + (size_t)b * NL * NL;

    const uint32_t shb = (uint32_t)__cvta_generic_to_shared(sh);
    const uint32_t k_loff =
        ((uint32_t)(wk * 32 + ((lane >> 4) << 3) + (lane & 7)) * 72 +
         (((lane >> 3) & 1) << 3)) * 2;
    const uint32_t v_loff =
        ((uint32_t)(wk * 32 + (((lane >> 3) & 1) << 3) + (lane & 7)) * 72 +
         ((lane >> 4) << 3)) * 2;

    const int ldr = tid >> 3, ldc = (tid & 7) * 8;

    auto loadQ = [&]() {
#pragma unroll
        for (int i = 0; i < 2; i++) {
            int r = ldr + 32 * i;
            cpa16(&Qs[r * 72 + ldc], Qg + (size_t)r * HD + ldc);
        }
    };
    auto loadK = [&](int buf, int ch) {
#pragma unroll
        for (int i = 0; i < 2; i++) {
            int r = ldr + 32 * i;
            cpa16(&Ks[buf * 4608 + r * 72 + ldc], Kg + (size_t)(ch * 64 + r) * HD + ldc);
        }
    };
    auto loadV = [&](int buf, int ch) {
#pragma unroll
        for (int i = 0; i < 2; i++) {
            int r = ldr + 32 * i;
            cpa16(&Vs[buf * 4608 + r * 72 + ldc], Vg + (size_t)(ch * 64 + r) * HD + ldc);
        }
    };

    const int rq  = wq * 16 + (lane >> 2);
    const int r0g = q0 + rq;
    const int kc  = (lane & 3) * 2;

    uint32_t qf[4][4];
    float lsum0 = 0.f, lsum1 = 0.f;

    // ---------------- sweep 1: row sums ----------------
    loadQ(); loadK(0, 0); cp_commit();
    for (int ch = 0; ch < 32; ch++) {
        if (ch < 31) { loadK((ch + 1) & 1, ch + 1); cp_commit(); cp_wait<1>(); }
        else         { cp_wait<0>(); }
        __syncthreads();
        if (ch == 0) {
#pragma unroll
            for (int s = 0; s < 4; s++) {
                int k0 = s * 16 + kc;
                qf[s][0] = *(const uint32_t*)&Qs[rq * 72 + k0];
                qf[s][1] = *(const uint32_t*)&Qs[(rq + 8) * 72 + k0];
                qf[s][2] = *(const uint32_t*)&Qs[rq * 72 + k0 + 8];
                qf[s][3] = *(const uint32_t*)&Qs[(rq + 8) * 72 + k0 + 8];
            }
        }
        const uint32_t ksb = shb + (uint32_t)(4608 + (ch & 1) * 4608) * 2 + k_loff;

        float acc[4][4];
#pragma unroll
        for (int j = 0; j < 4; j++)
#pragma unroll
            for (int e = 0; e < 4; e++) acc[j][e] = 0.f;
#pragma unroll
        for (int jp = 0; jp < 2; jp++)
#pragma unroll
            for (int s = 0; s < 4; s++) {
                uint32_t r[4];
                ldsm_x4(r, ksb + (uint32_t)(jp * 16 * 72 + s * 16) * 2);
                mma_f16(acc[2 * jp],     qf[s], &r[0]);
                mma_f16(acc[2 * jp + 1], qf[s], &r[2]);
            }
#pragma unroll
        for (int j = 0; j < 4; j++) {
            int colg = ch * 64 + wk * 32 + j * 8 + kc;
            float2 f0 = __half22float2(*(const __half2*)&mbb[(size_t)r0g * NL + colg]);
            float2 f1 = __half22float2(*(const __half2*)&mbb[(size_t)(r0g + 8) * NL + colg]);
            lsum0 += __expf(fmaf(acc[j][0], 0.125f, f0.x))
                   + __expf(fmaf(acc[j][1], 0.125f, f0.y));
            lsum1 += __expf(fmaf(acc[j][2], 0.125f, f1.x))
                   + __expf(fmaf(acc[j][3], 0.125f, f1.y));
        }
        __syncthreads();
    }
    lsum0 += __shfl_xor_sync(0xffffffffu, lsum0, 1);
    lsum0 += __shfl_xor_sync(0xffffffffu, lsum0, 2);
    lsum1 += __shfl_xor_sync(0xffffffffu, lsum1, 1);
    lsum1 += __shfl_xor_sync(0xffffffffu, lsum1, 2);
    if ((lane & 3) == 0) {
        lpart[wk * 64 + rq]     = lsum0;
        lpart[wk * 64 + rq + 8] = lsum1;
    }
    __syncthreads();
    if (tid < 64) invl[tid] = 1.0f / (lpart[tid] + lpart[64 + tid]);
    __syncthreads();

    const float il0 = invl[rq], il1 = invl[rq + 8];

    float oacc[8][4];
#pragma unroll
    for (int j = 0; j < 8; j++)
#pragma unroll
        for (int e = 0; e < 4; e++) oacc[j][e] = 0.f;

    // ---------------- sweep 2: attn write + P.V ----------------
    loadK(0, 0); loadV(0, 0); cp_commit();
    for (int ch = 0; ch < 32; ch++) {
        if (ch < 31) { loadK((ch + 1) & 1, ch + 1); loadV((ch + 1) & 1, ch + 1);
                       cp_commit(); cp_wait<1>(); }
        else         { cp_wait<0>(); }
        __syncthreads();
        const uint32_t ksb = shb + (uint32_t)(4608 + (ch & 1) * 4608) * 2 + k_loff;
        const uint32_t vsb = shb + (uint32_t)(3 * 4608 + (ch & 1) * 4608) * 2 + v_loff;

        float acc[4][4];
#pragma unroll
        for (int j = 0; j < 4; j++)
#pragma unroll
            for (int e = 0; e < 4; e++) acc[j][e] = 0.f;
#pragma unroll
        for (int jp = 0; jp < 2; jp++)
#pragma unroll
            for (int s = 0; s < 4; s++) {
                uint32_t r[4];
                ldsm_x4(r, ksb + (uint32_t)(jp * 16 * 72 + s * 16) * 2);
                mma_f16(acc[2 * jp],     qf[s], &r[0]);
                mma_f16(acc[2 * jp + 1], qf[s], &r[2]);
            }

        uint32_t pa[2][4];
#pragma unroll
        for (int j = 0; j < 4; j++) {
            int colg = ch * 64 + wk * 32 + j * 8 + kc;
            float2 f0 = __half22float2(*(const __half2*)&mbb[(size_t)r0g * NL + colg]);
            float2 f1 = __half22float2(*(const __half2*)&mbb[(size_t)(r0g + 8) * NL + colg]);
            float p0 = __expf(fmaf(acc[j][0], 0.125f, f0.x)) * il0;
            float p1 = __expf(fmaf(acc[j][1], 0.125f, f0.y)) * il0;
            float p2 = __expf(fmaf(acc[j][2], 0.125f, f1.x)) * il1;
            float p3 = __expf(fmaf(acc[j][3], 0.125f, f1.y)) * il1;
            *(float2*)&attn[((size_t)bh * NL + r0g) * NL + colg]     = make_float2(p0, p1);
            *(float2*)&attn[((size_t)bh * NL + r0g + 8) * NL + colg] = make_float2(p2, p3);
            int s2 = j >> 1;
            if ((j & 1) == 0) { pa[s2][0] = packh2(p0, p1); pa[s2][1] = packh2(p2, p3); }
            else              { pa[s2][2] = packh2(p0, p1); pa[s2][3] = packh2(p2, p3); }
        }
#pragma unroll
        for (int s2 = 0; s2 < 2; s2++)
#pragma unroll
            for (int jnp = 0; jnp < 4; jnp++) {
                uint32_t r[4];
                ldsm_x4_t(r, vsb + (uint32_t)(s2 * 16 * 72 + jnp * 16) * 2);
                mma_f16(oacc[2 * jnp],     pa[s2], &r[0]);
                mma_f16(oacc[2 * jnp + 1], pa[s2], &r[2]);
            }
        __syncthreads();
    }

    // ---------------- O reduction (wk pair) + ctx store (fp16) ----------------
    float* osum = (float*)Ks;   // 64 x 72 f32 = 18432 B, fits in Ks region
    if (wk == 1) {
#pragma unroll
        for (int jn = 0; jn < 8; jn++)
#pragma unroll
            for (int e = 0; e < 4; e++) {
                int row = wq * 16 + (lane >> 2) + (e >> 1) * 8;
                int col = jn * 8 + kc + (e & 1);
                osum[row * 72 + col] = oacc[jn][e];
            }
    }
    __syncthreads();
    if (wk == 0) {
#pragma unroll
        for (int jn = 0; jn < 8; jn++)
#pragma unroll
            for (int e = 0; e < 4; e++) {
                int row = wq * 16 + (lane >> 2) + (e >> 1) * 8;
                int col = jn * 8 + kc + (e & 1);
                osum[row * 72 + col] += oacc[jn][e];
            }
    }
    __syncthreads();
    for (int i = tid; i < 64 * 16; i += 256) {
        int row = i >> 4, c4 = (i & 15) * 4;
        float4 v = *(const float4*)&osum[row * 72 + c4];
        uint2 o = make_uint2(packh2(v.x, v.y), packh2(v.z, v.w));
        *(uint2*)&ctx[((size_t)b * NL + q0 + row) * ND + h * HD + c4] = o;
    }
}

// ============================================================================
// launch
// ============================================================================
extern "C" void kernel_launch(void* const* d_in, const int* in_sizes, int n_in,
                              void* d_out, int out_size) {
    (void)in_sizes; (void)n_in;
    const float* xs[3] = { (const float*)d_in[0], (const float*)d_in[1], (const float*)d_in[2] };
    const int*   msk = (const int*)d_in[3];
    const float* Ws[4] = { (const float*)d_in[4], (const float*)d_in[6],
                           (const float*)d_in[8], (const float*)d_in[10] };
    const float* bq = (const float*)d_in[5];
    const float* bk = (const float*)d_in[7];
    const float* bv = (const float*)d_in[9];
    const float* bo = (const float*)d_in[11];

    const long long FINAL_N = (long long)NB * NL * ND;
    const long long ATTN_N  = (long long)NBH * NL * NL;

    float* outp = (float*)d_out;
    float *finalp, *attnp;
    if ((long long)out_size >= FINAL_N + ATTN_N) { finalp = outp; attnp = outp + FINAL_N; }
    else if ((long long)out_size == ATTN_N)      { attnp = outp;  finalp = g_final; }
    else                                         { finalp = outp; attnp = g_attn; }

    const int SM_G16  = 4 * 5120 * 2;                       // 40,960 B
    const int SM_ATTN = 5 * 4608 * 2 + (64 + 128) * 4;      // 46,848 B

    cudaFuncSetAttribute(gemm16<1, __half>, cudaFuncAttributeMaxDynamicSharedMemorySize, SM_G16);
    cudaFuncSetAttribute(gemm16<0, float>,  cudaFuncAttributeMaxDynamicSharedMemorySize, SM_G16);
    cudaFuncSetAttribute(attn_fused, cudaFuncAttributeMaxDynamicSharedMemorySize, SM_ATTN);

    __half* qg;  cudaGetSymbolAddress((void**)&qg, g_qh);
    __half* kg;  cudaGetSymbolAddress((void**)&kg, g_kh);
    __half* vg;  cudaGetSymbolAddress((void**)&vg, g_vh);
    __half* xh;  cudaGetSymbolAddress((void**)&xh, g_xh);
    __half* wh;  cudaGetSymbolAddress((void**)&wh, g_wh);
    __half* mb;  cudaGetSymbolAddress((void**)&mb, g_mb);
    __half* cg;  cudaGetSymbolAddress((void**)&cg, g_ctxh);

    const size_t XN = (size_t)NB * NL * ND;      // 4,194,304
    const size_t WN = (size_t)ND * ND;           //   262,144
    const size_t MN = (size_t)NB * NL * NL;      // 16,777,216

    // conversions
    for (int i = 0; i < 3; i++)
        cvt_f16<<<(int)(XN / 4 / 256), 256>>>((const float4*)xs[i], (uint2*)(xh + i * XN), (int)(XN / 4));
    for (int i = 0; i < 4; i++)
        cvt_f16<<<(int)(WN / 4 / 256), 256>>>((const float4*)Ws[i], (uint2*)(wh + i * WN), (int)(WN / 4));
    cvt_maskbias<<<(int)(MN / 4 / 256), 256>>>((const int4*)msk, (uint2*)mb, (int)(MN / 4));

    // projections (fp16)
    dim3 gp(64, 4);
    gemm16<1, __half><<<gp, 256, SM_G16>>>(xh + 0 * XN, wh + 0 * WN, bq, qg);
    gemm16<1, __half><<<gp, 256, SM_G16>>>(xh + 1 * XN, wh + 1 * WN, bk, kg);
    gemm16<1, __half><<<gp, 256, SM_G16>>>(xh + 2 * XN, wh + 2 * WN, bv, vg);

    // fused attention
    attn_fused<<<dim3(NL / 64, NBH), 256, SM_ATTN>>>(qg, kg, vg, mb, attnp, cg);

    // output projection (fp16 inputs, fp32 out)
    gemm16<0, float><<<gp, 256, SM_G16>>>(cg, wh + 3 * WN, bo, finalp);
}

// round 15
// speedup vs baseline: 1.8920x; 1.0181x over previous
#include <cuda_runtime.h>
#include <cuda_fp16.h>
#include <cstdint>

#define DEVI __device__ __forceinline__

// ---- problem constants ----
#define NB 4
#define NL 2048
#define ND 512
#define NH 8
#define HD 64
#define NBH (NB*NH)

// ---- scratch ----
static __device__ __half g_qh[(size_t)NBH * NL * HD];
static __device__ __half g_kh[(size_t)NBH * NL * HD];
static __device__ __half g_vh[(size_t)NBH * NL * HD];
static __device__ __half g_xh[3][(size_t)NB * NL * ND];     // fp16 x_q, x_k, x_v
static __device__ __half g_wh[4][(size_t)ND * ND];          // fp16 Wq, Wk, Wv, Wo
static __device__ __half g_mb[(size_t)NB * NL * NL];        // fp16 mask bias (0 / -60000)
static __device__ __half g_ctxh[(size_t)NB * NL * ND];
static __device__ float  g_final[(size_t)NB * NL * ND];
static __device__ float  g_attn[(size_t)NBH * NL * NL];     // fallback if attn not in d_out

// ---- PTX helpers ----
DEVI void mma_f16(float c[4], const uint32_t a[4], const uint32_t b[2]) {
    asm volatile(
        "mma.sync.aligned.m16n8k16.row.col.f32.f16.f16.f32 "
        "{%0,%1,%2,%3},{%4,%5,%6,%7},{%8,%9},{%0,%1,%2,%3};"
        : "+f"(c[0]), "+f"(c[1]), "+f"(c[2]), "+f"(c[3])
        : "r"(a[0]), "r"(a[1]), "r"(a[2]), "r"(a[3]), "r"(b[0]), "r"(b[1]));
}
DEVI void ldsm_x4(uint32_t r[4], uint32_t addr) {
    asm volatile("ldmatrix.sync.aligned.m8n8.x4.shared.b16 {%0,%1,%2,%3}, [%4];"
        : "=r"(r[0]), "=r"(r[1]), "=r"(r[2]), "=r"(r[3]) : "r"(addr));
}
DEVI void ldsm_x4_t(uint32_t r[4], uint32_t addr) {
    asm volatile("ldmatrix.sync.aligned.m8n8.x4.trans.shared.b16 {%0,%1,%2,%3}, [%4];"
        : "=r"(r[0]), "=r"(r[1]), "=r"(r[2]), "=r"(r[3]) : "r"(addr));
}
DEVI void cpa16(void* s, const void* g) {
    uint32_t sa = (uint32_t)__cvta_generic_to_shared(s);
    asm volatile("cp.async.cg.shared.global [%0], [%1], 16;" :: "r"(sa), "l"(g));
}
DEVI void cp_commit() { asm volatile("cp.async.commit_group;"); }
template <int N> DEVI void cp_wait() { asm volatile("cp.async.wait_group %0;" :: "n"(N)); }
DEVI uint32_t packh2(float a, float b) {
    __half2 h = __floats2half2_rn(a, b);
    return *reinterpret_cast<uint32_t*>(&h);
}

// ============================================================================
// conversion kernels (one-time per launch, streaming)
// ============================================================================
__global__ void cvt_f16(const float4* __restrict__ in, uint2* __restrict__ out, int n4) {
    int i = blockIdx.x * blockDim.x + threadIdx.x;
    if (i < n4) {
        float4 v = in[i];
        out[i] = make_uint2(packh2(v.x, v.y), packh2(v.z, v.w));
    }
}
__global__ void cvt_maskbias(const int4* __restrict__ in, uint2* __restrict__ out, int n4) {
    int i = blockIdx.x * blockDim.x + threadIdx.x;
    if (i < n4) {
        int4 m = in[i];
        out[i] = make_uint2(
            packh2(m.x ? -60000.f : 0.f, m.y ? -60000.f : 0.f),
            packh2(m.z ? -60000.f : 0.f, m.w ? -60000.f : 0.f));
    }
}

// ============================================================================
// fp16 TN GEMM (unchanged from R11): out[m,n] = sum_k A[m,k]*W[n,k] + bias[n]
// ============================================================================
template <int PERM, typename OutT>
__global__ __launch_bounds__(256, 2) void gemm16(
    const __half* __restrict__ A, const __half* __restrict__ W,
    const float* __restrict__ bias, OutT* __restrict__ out)
{
    extern __shared__ __align__(16) __half smh[];
    __half* As = smh;             // [2][128*40]
    __half* Bs = smh + 2 * 5120;  // [2][128*40]
    const int tid = threadIdx.x, lane = tid & 31, wid = tid >> 5;
    const int wm = wid & 3, wn = wid >> 2;
    const int m0 = blockIdx.x * 128, n0 = blockIdx.y * 128;
    const uint32_t shb = (uint32_t)__cvta_generic_to_shared(smh);

    float acc[2][8][4];
#pragma unroll
    for (int i = 0; i < 2; i++)
#pragma unroll
        for (int j = 0; j < 8; j++)
#pragma unroll
            for (int e = 0; e < 4; e++) acc[i][j][e] = 0.f;

    const int lr = tid >> 1, lc = (tid & 1) * 16;
    auto load_tile = [&](int buf, int kt) {
        const __half* ag = A + (size_t)(m0 + lr) * 512 + kt * 32 + lc;
        const __half* bg = W + (size_t)(n0 + lr) * 512 + kt * 32 + lc;
        __half* as = &As[buf * 5120 + lr * 40 + lc];
        __half* bs = &Bs[buf * 5120 + lr * 40 + lc];
        cpa16(as,     ag);
        cpa16(as + 8, ag + 8);
        cpa16(bs,     bg);
        cpa16(bs + 8, bg + 8);
        cp_commit();
    };
    const uint32_t a_loff =
        ((uint32_t)((lane & 7) + ((lane >> 3) & 1) * 8) * 40 + (lane >> 4) * 8) * 2;
    const uint32_t b_loff =
        ((uint32_t)((lane & 7) + ((lane >> 4) << 3)) * 40 + ((lane >> 3) & 1) * 8) * 2;

    load_tile(0, 0);
    for (int kt = 0; kt < 16; kt++) {
        if (kt < 15) { load_tile((kt + 1) & 1, kt + 1); cp_wait<1>(); }
        else         { cp_wait<0>(); }
        __syncthreads();
        const uint32_t abase = shb + (uint32_t)((kt & 1) * 5120) * 2 + a_loff;
        const uint32_t bbase = shb + (uint32_t)(2 * 5120 + (kt & 1) * 5120) * 2 + b_loff;
#pragma unroll
        for (int ks = 0; ks < 2; ks++) {
            uint32_t af[2][4], bf[4][4];
#pragma unroll
            for (int mi = 0; mi < 2; mi++)
                ldsm_x4(af[mi], abase + (uint32_t)((wm * 32 + mi * 16) * 40 + ks * 16) * 2);
#pragma unroll
            for (int jn = 0; jn < 4; jn++)
                ldsm_x4(bf[jn], bbase + (uint32_t)((wn * 64 + jn * 16) * 40 + ks * 16) * 2);
#pragma unroll
            for (int mi = 0; mi < 2; mi++)
#pragma unroll
                for (int jn = 0; jn < 4; jn++) {
                    mma_f16(acc[mi][2 * jn],     af[mi], &bf[jn][0]);
                    mma_f16(acc[mi][2 * jn + 1], af[mi], &bf[jn][2]);
                }
        }
        __syncthreads();
    }

#pragma unroll
    for (int i = 0; i < 2; i++)
#pragma unroll
        for (int j = 0; j < 8; j++)
#pragma unroll
            for (int e = 0; e < 4; e++) {
                int row = m0 + wm * 32 + i * 16 + (lane >> 2) + ((e >> 1) * 8);
                int col = n0 + wn * 64 + j * 8 + ((lane & 3) * 2) + (e & 1);
                float v = acc[i][j][e] + __ldg(&bias[col]);
                if (PERM) {
                    int bb = row >> 11, l = row & (NL - 1);
                    out[(((size_t)(bb * NH + (col >> 6))) * NL + l) * HD + (col & 63)] = (OutT)v;
                } else {
                    out[(size_t)row * ND + col] = (OutT)v;
                }
            }
}

// ============================================================================
// Fused attention, 128 q-rows/CTA, no k-split. 8 warps = 8 x 16 q-rows.
// Each warp processes the FULL 64-key chunk for its 16 rows (8 QK acc chains,
// 2x the MMA ILP of the previous version; no cross-warp O reduction).
//   Sweep 1: QK^T -> exp(s/8 + bias) -> row sums l
//   Sweep 2: recompute QK^T -> p = exp*il -> attn write + P.V -> ctx (fp16)
// smem: Qs[128][72] + Ks[2][64][72] + Vs[2][64][72] (half) + invl/lpart[128]
//       = 56,320 B; osum (128x72 f32) overlays the Ks+Vs region at the end.
// ============================================================================
__global__ __launch_bounds__(256, 2) void attn_fused(
    const __half* __restrict__ Q, const __half* __restrict__ K,
    const __half* __restrict__ V, const __half* __restrict__ mbias,
    float* __restrict__ attn, __half* __restrict__ ctx)
{
    extern __shared__ __align__(16) __half sh[];
    __half* Qs = sh;                         // 128*72
    __half* Ks = sh + 9216;                  // 2 * 64*72
    __half* Vs = sh + 18432;                 // 2 * 64*72
    float* invl  = (float*)(sh + 27648);     // 128
    float* lpart = invl + 128;               // 128

    const int tid = threadIdx.x, lane = tid & 31, wid = tid >> 5;
    const int wq = wid;                      // 16 q-rows per warp
    const int bh = blockIdx.y, b = bh >> 3, h = bh & 7;
    const int q0 = blockIdx.x * 128;

    const __half* Qg = Q + ((size_t)bh * NL + q0) * HD;
    const __half* Kg = K + (size_t)bh * NL * HD;
    const __half* Vg = V + (size_t)bh * NL * HD;
    const __half* mbb = mbias + (size_t)b * NL * NL;

    const uint32_t shb = (uint32_t)__cvta_generic_to_shared(sh);
    const uint32_t k_loff =
        ((uint32_t)(((lane >> 4) << 3) + (lane & 7)) * 72 + (((lane >> 3) & 1) << 3)) * 2;
    const uint32_t v_loff =
        ((uint32_t)((((lane >> 3) & 1) << 3) + (lane & 7)) * 72 + ((lane >> 4) << 3)) * 2;

    const int ldr = tid >> 3, ldc = (tid & 7) * 8;

    auto loadQ = [&]() {
#pragma unroll
        for (int i = 0; i < 4; i++) {
            int r = ldr + 32 * i;
            cpa16(&Qs[r * 72 + ldc], Qg + (size_t)r * HD + ldc);
        }
    };
    auto loadK = [&](int buf, int ch) {
#pragma unroll
        for (int i = 0; i < 2; i++) {
            int r = ldr + 32 * i;
            cpa16(&Ks[buf * 4608 + r * 72 + ldc], Kg + (size_t)(ch * 64 + r) * HD + ldc);
        }
    };
    auto loadV = [&](int buf, int ch) {
#pragma unroll
        for (int i = 0; i < 2; i++) {
            int r = ldr + 32 * i;
            cpa16(&Vs[buf * 4608 + r * 72 + ldc], Vg + (size_t)(ch * 64 + r) * HD + ldc);
        }
    };

    const int rq  = wq * 16 + (lane >> 2);     // local q row (and +8)
    const int r0g = q0 + rq;                   // global q row
    const int kc  = (lane & 3) * 2;

    uint32_t qf[4][4];                         // Q A-frags, reused both sweeps
    float lsum0 = 0.f, lsum1 = 0.f;

    // ---------------- sweep 1: row sums ----------------
    loadQ(); loadK(0, 0); cp_commit();
    for (int ch = 0; ch < 32; ch++) {
        if (ch < 31) { loadK((ch + 1) & 1, ch + 1); cp_commit(); cp_wait<1>(); }
        else         { cp_wait<0>(); }
        __syncthreads();
        if (ch == 0) {
#pragma unroll
            for (int s = 0; s < 4; s++) {
                int k0 = s * 16 + kc;
                qf[s][0] = *(const uint32_t*)&Qs[rq * 72 + k0];
                qf[s][1] = *(const uint32_t*)&Qs[(rq + 8) * 72 + k0];
                qf[s][2] = *(const uint32_t*)&Qs[rq * 72 + k0 + 8];
                qf[s][3] = *(const uint32_t*)&Qs[(rq + 8) * 72 + k0 + 8];
            }
        }
        const uint32_t ksb = shb + (uint32_t)(9216 + (ch & 1) * 4608) * 2 + k_loff;

        float acc[8][4];
#pragma unroll
        for (int j = 0; j < 8; j++)
#pragma unroll
            for (int e = 0; e < 4; e++) acc[j][e] = 0.f;
#pragma unroll
        for (int jp = 0; jp < 4; jp++)
#pragma unroll
            for (int s = 0; s < 4; s++) {
                uint32_t r[4];
                ldsm_x4(r, ksb + (uint32_t)(jp * 16 * 72 + s * 16) * 2);
                mma_f16(acc[2 * jp],     qf[s], &r[0]);
                mma_f16(acc[2 * jp + 1], qf[s], &r[2]);
            }
#pragma unroll
        for (int j = 0; j < 8; j++) {
            int colg = ch * 64 + j * 8 + kc;
            float2 f0 = __half22float2(*(const __half2*)&mbb[(size_t)r0g * NL + colg]);
            float2 f1 = __half22float2(*(const __half2*)&mbb[(size_t)(r0g + 8) * NL + colg]);
            lsum0 += __expf(fmaf(acc[j][0], 0.125f, f0.x))
                   + __expf(fmaf(acc[j][1], 0.125f, f0.y));
            lsum1 += __expf(fmaf(acc[j][2], 0.125f, f1.x))
                   + __expf(fmaf(acc[j][3], 0.125f, f1.y));
        }
        __syncthreads();
    }
    lsum0 += __shfl_xor_sync(0xffffffffu, lsum0, 1);
    lsum0 += __shfl_xor_sync(0xffffffffu, lsum0, 2);
    lsum1 += __shfl_xor_sync(0xffffffffu, lsum1, 1);
    lsum1 += __shfl_xor_sync(0xffffffffu, lsum1, 2);
    if ((lane & 3) == 0) {
        lpart[rq]     = lsum0;
        lpart[rq + 8] = lsum1;
    }
    __syncthreads();
    if (tid < 128) invl[tid] = 1.0f / lpart[tid];
    __syncthreads();

    const float il0 = invl[rq], il1 = invl[rq + 8];

    float oacc[8][4];
#pragma unroll
    for (int j = 0; j < 8; j++)
#pragma unroll
        for (int e = 0; e < 4; e++) oacc[j][e] = 0.f;

    // ---------------- sweep 2: attn write + P.V ----------------
    loadK(0, 0); loadV(0, 0); cp_commit();
    for (int ch = 0; ch < 32; ch++) {
        if (ch < 31) { loadK((ch + 1) & 1, ch + 1); loadV((ch + 1) & 1, ch + 1);
                       cp_commit(); cp_wait<1>(); }
        else         { cp_wait<0>(); }
        __syncthreads();
        const uint32_t ksb = shb + (uint32_t)(9216  + (ch & 1) * 4608) * 2 + k_loff;
        const uint32_t vsb = shb + (uint32_t)(18432 + (ch & 1) * 4608) * 2 + v_loff;

        float acc[8][4];
#pragma unroll
        for (int j = 0; j < 8; j++)
#pragma unroll
            for (int e = 0; e < 4; e++) acc[j][e] = 0.f;
#pragma unroll
        for (int jp = 0; jp < 4; jp++)
#pragma unroll
            for (int s = 0; s < 4; s++) {
                uint32_t r[4];
                ldsm_x4(r, ksb + (uint32_t)(jp * 16 * 72 + s * 16) * 2);
                mma_f16(acc[2 * jp],     qf[s], &r[0]);
                mma_f16(acc[2 * jp + 1], qf[s], &r[2]);
            }

        uint32_t pa[4][4];
#pragma unroll
        for (int j = 0; j < 8; j++) {
            int colg = ch * 64 + j * 8 + kc;
            float2 f0 = __half22float2(*(const __half2*)&mbb[(size_t)r0g * NL + colg]);
            float2 f1 = __half22float2(*(const __half2*)&mbb[(size_t)(r0g + 8) * NL + colg]);
            float p0 = __expf(fmaf(acc[j][0], 0.125f, f0.x)) * il0;
            float p1 = __expf(fmaf(acc[j][1], 0.125f, f0.y)) * il0;
            float p2 = __expf(fmaf(acc[j][2], 0.125f, f1.x)) * il1;
            float p3 = __expf(fmaf(acc[j][3], 0.125f, f1.y)) * il1;
            *(float2*)&attn[((size_t)bh * NL + r0g) * NL + colg]     = make_float2(p0, p1);
            *(float2*)&attn[((size_t)bh * NL + r0g + 8) * NL + colg] = make_float2(p2, p3);
            int s2 = j >> 1;
            if ((j & 1) == 0) { pa[s2][0] = packh2(p0, p1); pa[s2][1] = packh2(p2, p3); }
            else              { pa[s2][2] = packh2(p0, p1); pa[s2][3] = packh2(p2, p3); }
        }
#pragma unroll
        for (int s2 = 0; s2 < 4; s2++)
#pragma unroll
            for (int jnp = 0; jnp < 4; jnp++) {
                uint32_t r[4];
                ldsm_x4_t(r, vsb + (uint32_t)(s2 * 16 * 72 + jnp * 16) * 2);
                mma_f16(oacc[2 * jnp],     pa[s2], &r[0]);
                mma_f16(oacc[2 * jnp + 1], pa[s2], &r[2]);
            }
        __syncthreads();
    }

    // ---------------- ctx store (fp16), per-warp rows, smem staging ----------
    float* osum = (float*)Ks;   // 128 x 72 f32 = 36,864 B = Ks+Vs regions
#pragma unroll
    for (int jn = 0; jn < 8; jn++)
#pragma unroll
        for (int e = 0; e < 4; e++) {
            int row = wq * 16 + (lane >> 2) + (e >> 1) * 8;
            int col = jn * 8 + kc + (e & 1);
            osum[row * 72 + col] = oacc[jn][e];
        }
    __syncthreads();
    for (int i = tid; i < 128 * 16; i += 256) {
        int row = i >> 4, c4 = (i & 15) * 4;
        float4 v = *(const float4*)&osum[row * 72 + c4];
        uint2 o = make_uint2(packh2(v.x, v.y), packh2(v.z, v.w));
        *(uint2*)&ctx[((size_t)b * NL + q0 + row) * ND + h * HD + c4] = o;
    }
}

// ============================================================================
// launch
// ============================================================================
extern "C" void kernel_launch(void* const* d_in, const int* in_sizes, int n_in,
                              void* d_out, int out_size) {
    (void)in_sizes; (void)n_in;
    const float* xs[3] = { (const float*)d_in[0], (const float*)d_in[1], (const float*)d_in[2] };
    const int*   msk = (const int*)d_in[3];
    const float* Ws[4] = { (const float*)d_in[4], (const float*)d_in[6],
                           (const float*)d_in[8], (const float*)d_in[10] };
    const float* bq = (const float*)d_in[5];
    const float* bk = (const float*)d_in[7];
    const float* bv = (const float*)d_in[9];
    const float* bo = (const float*)d_in[11];

    const long long FINAL_N = (long long)NB * NL * ND;
    const long long ATTN_N  = (long long)NBH * NL * NL;

    float* outp = (float*)d_out;
    float *finalp, *attnp;
    if ((long long)out_size >= FINAL_N + ATTN_N) { finalp = outp; attnp = outp + FINAL_N; }
    else if ((long long)out_size == ATTN_N)      { attnp = outp;  finalp = g_final; }
    else                                         { finalp = outp; attnp = g_attn; }

    const int SM_G16  = 4 * 5120 * 2;                       // 40,960 B
    const int SM_ATTN = 27648 * 2 + 256 * 4;                // 56,320 B

    cudaFuncSetAttribute(gemm16<1, __half>, cudaFuncAttributeMaxDynamicSharedMemorySize, SM_G16);
    cudaFuncSetAttribute(gemm16<0, float>,  cudaFuncAttributeMaxDynamicSharedMemorySize, SM_G16);
    cudaFuncSetAttribute(attn_fused, cudaFuncAttributeMaxDynamicSharedMemorySize, SM_ATTN);

    __half* qg;  cudaGetSymbolAddress((void**)&qg, g_qh);
    __half* kg;  cudaGetSymbolAddress((void**)&kg, g_kh);
    __half* vg;  cudaGetSymbolAddress((void**)&vg, g_vh);
    __half* xh;  cudaGetSymbolAddress((void**)&xh, g_xh);
    __half* wh;  cudaGetSymbolAddress((void**)&wh, g_wh);
    __half* mb;  cudaGetSymbolAddress((void**)&mb, g_mb);
    __half* cg;  cudaGetSymbolAddress((void**)&cg, g_ctxh);

    const size_t XN = (size_t)NB * NL * ND;      // 4,194,304
    const size_t WN = (size_t)ND * ND;           //   262,144
    const size_t MN = (size_t)NB * NL * NL;      // 16,777,216

    // conversions
    for (int i = 0; i < 3; i++)
        cvt_f16<<<(int)(XN / 4 / 256), 256>>>((const float4*)xs[i], (uint2*)(xh + i * XN), (int)(XN / 4));
    for (int i = 0; i < 4; i++)
        cvt_f16<<<(int)(WN / 4 / 256), 256>>>((const float4*)Ws[i], (uint2*)(wh + i * WN), (int)(WN / 4));
    cvt_maskbias<<<(int)(MN / 4 / 256), 256>>>((const int4*)msk, (uint2*)mb, (int)(MN / 4));

    // projections (fp16)
    dim3 gp(64, 4);
    gemm16<1, __half><<<gp, 256, SM_G16>>>(xh + 0 * XN, wh + 0 * WN, bq, qg);
    gemm16<1, __half><<<gp, 256, SM_G16>>>(xh + 1 * XN, wh + 1 * WN, bk, kg);
    gemm16<1, __half><<<gp, 256, SM_G16>>>(xh + 2 * XN, wh + 2 * WN, bv, vg);

    // fused attention: 128 q-rows per CTA
    attn_fused<<<dim3(NL / 128, NBH), 256, SM_ATTN>>>(qg, kg, vg, mb, attnp, cg);

    // output projection (fp16 inputs, fp32 out)
    gemm16<0, float><<<gp, 256, SM_G16>>>(cg, wh + 3 * WN, bo, finalp);
}